// round 12
// baseline (speedup 1.0000x reference)
// GCN + EdgePool forward — R12: endpoint-only best-buffer resets in zMatch tail
// (full-Nn zero sweep only while 2n >= Nn); layer-2 dinv+gemm fused.
#include <cuda_runtime.h>
#include <math.h>

#define Nn 60000
#define Ee 600000
#define Ff 384
#define Hh 6
#define Cc 10
#define Bb 8
#define TAB (1u<<21)
#define TABM (TAB-1u)
#define NT 256

// ---------------- scratch (static device globals; no allocation) ----------------
__device__ float g_t1[Nn*Hh];
__device__ float g_acc1[Nn*Hh];
__device__ float g_h1[Nn*Hh];
__device__ float g_x1[Nn*Hh];
__device__ float g_t2[Nn*Cc];
__device__ float g_acc2[Nn*Cc];
__device__ float g_h2[Nn*Cc];
__device__ float g_x2[Nn*Cc];

__device__ int   g_degI[Nn];
__device__ int   g_hasloop[Nn];
__device__ unsigned char g_addloop[Nn];
__device__ float g_dinv[Nn];

__device__ unsigned g_m[Nn];
__device__ float g_mf[Nn];
__device__ float g_s[Nn];
__device__ float g_raw[Ee];
__device__ float g_ex[Ee];
__device__ float g_score[Ee];
__device__ unsigned long long g_prio[Ee];

__device__ unsigned long long g_best[3][Nn];
__device__ int g_alive[Nn];
__device__ int   g_list[2][Ee];
__device__ int   g_cntL[3];
__device__ int   g_partner[Nn];
__device__ float g_scale[Nn];
__device__ unsigned char g_dead[Nn];
__device__ int   g_cmapSrc[Nn];
__device__ int   g_cmap[Nn];
__device__ int   g_ns[Ee];
__device__ int   g_nd[Ee];
__device__ unsigned char g_ev1[Ee];
__device__ unsigned char g_nv0[Nn];
__device__ unsigned char g_nv1[Nn];
__device__ unsigned char g_nv2[Nn];

__device__ unsigned g_hkey[TAB];
__device__ unsigned g_hval[TAB];

__device__ float g_cnt[Bb];
__device__ float g_sum[Bb*Cc];

__device__ unsigned g_barCount;
__device__ volatile unsigned g_barGen;

// ---------------- helpers ----------------
__device__ __forceinline__ unsigned fkey(float f){
    unsigned b = __float_as_uint(f);
    return b ^ (((int)b >> 31) ? 0xFFFFFFFFu : 0x80000000u);
}
__device__ __forceinline__ float finv(unsigned k){
    unsigned b = (k & 0x80000000u) ? (k ^ 0x80000000u) : ~k;
    return __uint_as_float(b);
}

// ---------------- init ----------------
__global__ void zInitMain(){
    int stride = gridDim.x*blockDim.x;
    for(unsigned i = blockIdx.x*blockDim.x + threadIdx.x; i < TAB; i += stride){
        g_hkey[i] = 0xFFFFFFFFu; g_hval[i] = 0xFFFFFFFFu;
        if(i < Nn*Cc) g_acc2[i] = 0.f;
        if(i < Nn*Hh) g_acc1[i] = 0.f;
        if(i < Nn){ g_degI[i]=0; g_hasloop[i]=0; g_m[i]=0u; g_s[i]=0.f; g_nv0[i]=1; }
        if(i < Bb)    g_cnt[i]=0.f;
        if(i < Bb*Cc) g_sum[i]=0.f;
        if(i == 0){ g_barCount = 0u; }
    }
}

__global__ void zInit2(){
    int v = blockIdx.x*blockDim.x + threadIdx.x;
    if(v < Nn){ g_degI[v]=0; g_hasloop[v]=0; g_m[v]=0u; g_s[v]=0.f; }
}

// ---------------- GEMM1: t1 = x @ W1  (60000x384 @ 384x6, exact fp32) ----------
__global__ void zGemm1(const float* __restrict__ x, const float* __restrict__ W1,
                       float* __restrict__ t1){
    __shared__ float Ws[Ff*Hh];
    for(int i = threadIdx.x; i < Ff*Hh; i += blockDim.x) Ws[i] = W1[i];
    __syncthreads();
    int warp = threadIdx.x >> 5, lane = threadIdx.x & 31;
    int row = blockIdx.x*8 + warp;
    if(row >= Nn) return;
    const float* xr = x + (size_t)row*Ff;
    float a0=0,a1=0,a2=0,a3=0,a4=0,a5=0;
    for(int k = lane; k < Ff; k += 32){
        float xv = xr[k];
        const float* w = Ws + k*Hh;
        a0 += xv*w[0]; a1 += xv*w[1]; a2 += xv*w[2];
        a3 += xv*w[3]; a4 += xv*w[4]; a5 += xv*w[5];
    }
    #pragma unroll
    for(int off = 16; off; off >>= 1){
        a0 += __shfl_down_sync(0xffffffffu, a0, off);
        a1 += __shfl_down_sync(0xffffffffu, a1, off);
        a2 += __shfl_down_sync(0xffffffffu, a2, off);
        a3 += __shfl_down_sync(0xffffffffu, a3, off);
        a4 += __shfl_down_sync(0xffffffffu, a4, off);
        a5 += __shfl_down_sync(0xffffffffu, a5, off);
    }
    if(lane == 0){
        float* o = t1 + (size_t)row*Hh;
        o[0]=a0; o[1]=a1; o[2]=a2; o[3]=a3; o[4]=a4; o[5]=a5;
    }
}

// ---------------- layer-2 fused: dinv + t2 = x1 @ W2 ---------------------------
__global__ void zDinvGemm2(const unsigned char* __restrict__ nv,
                           const float* __restrict__ x1, const float* __restrict__ W2,
                           float* __restrict__ t2){
    int v = blockIdx.x*blockDim.x + threadIdx.x;
    if(v >= Nn) return;
    int add = (nv[v] && !g_hasloop[v]) ? 1 : 0;
    g_addloop[v] = (unsigned char)add;
    int dg = g_degI[v] + add;
    g_dinv[v] = (dg > 0) ? 1.0f/sqrtf((float)dg) : 0.0f;
    float xr[Hh];
    #pragma unroll
    for(int j = 0; j < Hh; j++) xr[j] = x1[v*Hh + j];
    #pragma unroll
    for(int c = 0; c < Cc; c++){
        float a = 0.f;
        #pragma unroll
        for(int j = 0; j < Hh; j++) a += xr[j]*W2[j*Cc + c];
        t2[v*Cc + c] = a;
    }
}

// ---------------- degree / dinv ----------------
__global__ void zDeg(const int* __restrict__ sA, const int* __restrict__ dA){
    int e = blockIdx.x*blockDim.x + threadIdx.x;
    if(e >= Ee) return;
    int d = dA[e];
    atomicAdd(&g_degI[d], 1);
    if(sA[e] == d) g_hasloop[d] = 1;
}

__global__ void zDinv(const unsigned char* __restrict__ nv){
    int v = blockIdx.x*blockDim.x + threadIdx.x;
    if(v >= Nn) return;
    int add = (nv[v] && !g_hasloop[v]) ? 1 : 0;
    g_addloop[v] = (unsigned char)add;
    int dg = g_degI[v] + add;
    g_dinv[v] = (dg > 0) ? 1.0f/sqrtf((float)dg) : 0.0f;
}

template<int FD>
__global__ void zAgg(const int* __restrict__ sA, const int* __restrict__ dA,
                     const unsigned char* __restrict__ ev,
                     const float* __restrict__ t, float* __restrict__ acc){
    int e = blockIdx.x*blockDim.x + threadIdx.x;
    if(e >= Ee) return;
    if(ev && !ev[e]) return;
    int s = sA[e], d = dA[e];
    float c = g_dinv[s]*g_dinv[d];
    #pragma unroll
    for(int j = 0; j < FD; j++)
        atomicAdd(&acc[(size_t)d*FD + j], t[(size_t)s*FD + j]*c);
}

template<int FD, bool RELU>
__global__ void zFinishGcn(const float* __restrict__ acc, const float* __restrict__ t,
                           const float* __restrict__ bias, float* __restrict__ out){
    int v = blockIdx.x*blockDim.x + threadIdx.x;
    if(v >= Nn) return;
    float di = g_dinv[v];
    float al = g_addloop[v] ? di*di : 0.0f;
    #pragma unroll
    for(int j = 0; j < FD; j++){
        float o = acc[(size_t)v*FD + j] + al*t[(size_t)v*FD + j] + bias[j];
        out[(size_t)v*FD + j] = RELU ? fmaxf(o, 0.0f) : o;
    }
}

// ---------------- edge pool: score pipeline ----------------
template<int FD>
__global__ void zRawMax(const float* __restrict__ xf, const int* __restrict__ sA,
                        const int* __restrict__ dA, const unsigned char* __restrict__ ev,
                        const float* __restrict__ Wp, const float* __restrict__ bp){
    int e = blockIdx.x*blockDim.x + threadIdx.x;
    if(e >= Ee) return;
    int s = sA[e], d = dA[e];
    float r = bp[0];
    #pragma unroll
    for(int j = 0; j < FD; j++) r += xf[(size_t)s*FD + j]*Wp[j];
    #pragma unroll
    for(int j = 0; j < FD; j++) r += xf[(size_t)d*FD + j]*Wp[FD + j];
    g_raw[e] = r;
    bool valid = ev ? (ev[e] != 0) : true;
    if(valid) atomicMax(&g_m[d], fkey(r));
}

// fused: mf finalize + alive/pool state init + best[0..1]/counters reset
__global__ void zNodePrep(const unsigned char* __restrict__ nv){
    int v = blockIdx.x*blockDim.x + threadIdx.x;
    if(v >= Nn) return;
    unsigned k = g_m[v];
    g_mf[v] = (k == 0u) ? 0.0f : finv(k);
    g_alive[v]   = nv[v] ? 1 : 0;
    g_partner[v] = -1;
    g_scale[v]   = 1.0f;
    g_dead[v]    = 0;
    g_cmapSrc[v] = -1;
    g_best[0][v] = 0ull;
    g_best[1][v] = 0ull;
    if(v == 0){ g_cntL[0] = 0; g_cntL[1] = 0; g_cntL[2] = 0; }
}

__global__ void zEx(const int* __restrict__ dA, const unsigned char* __restrict__ ev){
    int e = blockIdx.x*blockDim.x + threadIdx.x;
    if(e >= Ee) return;
    bool valid = ev ? (ev[e] != 0) : true;
    float exv = 0.0f;
    if(valid){
        int d = dA[e];
        exv = expf(g_raw[e] - g_mf[d]);
        atomicAdd(&g_s[d], exv);
    }
    g_ex[e] = exv;
}

// score + initial list + round-0 priority posting (phase-1 of round 0)
__global__ void zScore(const int* __restrict__ sA, const int* __restrict__ dA,
                       const unsigned char* __restrict__ ev){
    int e = blockIdx.x*blockDim.x + threadIdx.x;
    if(e >= Ee) return;
    bool valid = ev ? (ev[e] != 0) : true;
    unsigned long long p = 0ull;
    if(valid){
        int d = dA[e];
        float sv = g_s[d];
        float sc = g_ex[e]/((sv > 0.f) ? sv : 1.f) + 0.5f;
        g_score[e] = sc;
        // total priority = (score desc, edge index asc) == stable argsort(-score)
        p = ((unsigned long long)fkey(sc) << 32)
          | (unsigned long long)(0xFFFFFFFFu - (unsigned)e);
        g_prio[e] = p;
        atomicMax(&g_best[0][sA[e]], p);
        atomicMax(&g_best[0][d], p);
    }
    unsigned mask = __ballot_sync(0xffffffffu, valid);   // Ee % 32 == 0: full warps
    if(valid){
        int lane = threadIdx.x & 31;
        int leader = __ffs(mask) - 1;
        int base = 0;
        if(lane == leader) base = atomicAdd(&g_cntL[0], __popc(mask));
        base = __shfl_sync(mask, base, leader);
        g_list[0][base + __popc(mask & ((1u << lane) - 1u))] = e;
    }
}

// ---------------- persistent matching (locally-dominant == sequential greedy) ----
__device__ __forceinline__ void gbar(){
    __syncthreads();
    if(threadIdx.x == 0){
        __threadfence();
        unsigned gen = g_barGen;
        if(atomicAdd(&g_barCount, 1u) == gridDim.x - 1u){
            g_barCount = 0u;
            __threadfence();
            g_barGen = gen + 1u;
        } else {
            while(g_barGen == gen){ __nanosleep(64); }
            __threadfence();
        }
    }
    __syncthreads();
}

// on-chosen pool apply (arrays read only after kernel end)
__device__ __forceinline__ void applyChosen(int e, int s, int d){
    g_alive[s] = 0;
    g_alive[d] = 0;
    g_scale[s] = g_score[e];
    if(s != d){
        g_partner[s] = d;
        g_dead[d] = 1;
        g_cmapSrc[d] = s;
    }
}

// One sweep + ONE grid barrier per round; 3-buffer best rotation.
// Zero-buffer reset: endpoint-only when the frontier is small (safe because
// posts in round r target endpoints of list_{r+1} ⊆ list_r, and that buffer was
// reset at endpoints of list_{r-1} ⊇ list_r before posting).
__global__ void zMatch(const int* __restrict__ sA, const int* __restrict__ dA){
    const int gid = blockIdx.x*blockDim.x + threadIdx.x;
    const int gsz = gridDim.x*blockDim.x;
    const int lane = threadIdx.x & 31;
    volatile int* vAlive = (volatile int*)g_alive;
    int rb = 0;    // read-buffer / counter index
    int cur = 0;   // list ping-pong
    for(int round = 0; round < 100000; round++){
        int n = *((volatile int*)&g_cntL[rb]);
        if(n == 0) break;
        int pb = rb + 1; if(pb == 3) pb = 0;
        int zb = pb + 1; if(zb == 3) zb = 0;
        volatile unsigned long long* bestR = (volatile unsigned long long*)g_best[rb];
        unsigned long long* bestP = g_best[pb];
        unsigned long long* bestZ = g_best[zb];
        volatile const int* vlst = (volatile const int*)g_list[cur];
        int* onxt = g_list[cur^1];
        // reset round-after-next buffer + counter
        if(2*n >= Nn){
            for(int v = gid; v < Nn; v += gsz) bestZ[v] = 0ull;
        } else {
            for(int i = gid; i < n; i += gsz){
                int e = vlst[i];
                bestZ[sA[e]] = 0ull;
                bestZ[dA[e]] = 0ull;
            }
        }
        if(gid == 0) g_cntL[zb] = 0;
        // fused choose + survivor-post sweep
        for(int i = gid; i < n; i += gsz){
            int e = vlst[i];
            int s = sA[e], d = dA[e];
            bool keep = false;
            unsigned long long p = 0ull;
            if(vAlive[s] && vAlive[d]){
                p = g_prio[e];
                if(bestR[s] == p && bestR[d] == p) applyChosen(e, s, d);
                else keep = true;
            }
            unsigned act = __activemask();
            unsigned mask = __ballot_sync(act, keep);
            if(keep){
                atomicMax(&bestP[s], p);
                atomicMax(&bestP[d], p);
                int leader = __ffs(mask) - 1;
                int base = 0;
                if(lane == leader) base = atomicAdd(&g_cntL[pb], __popc(mask));
                base = __shfl_sync(mask, base, leader);
                onxt[base + __popc(mask & ((1u << lane) - 1u))] = e;
            }
        }
        gbar();
        rb = pb; cur ^= 1;
    }
}

template<int FD>
__global__ void zPoolNode(const float* __restrict__ xin, float* __restrict__ xout,
                          const unsigned char* __restrict__ nvin, unsigned char* __restrict__ nvout){
    int v = blockIdx.x*blockDim.x + threadIdx.x;
    if(v >= Nn) return;
    unsigned char nv = (nvin[v] && !g_dead[v]) ? 1 : 0;
    nvout[v] = nv;
    int cs = g_cmapSrc[v];
    g_cmap[v] = (cs >= 0) ? cs : v;
    float scl = g_scale[v];
    int p = g_partner[v];
    #pragma unroll
    for(int j = 0; j < FD; j++){
        float val = xin[(size_t)v*FD + j] + ((p >= 0) ? xin[(size_t)p*FD + j] : 0.0f);
        xout[(size_t)v*FD + j] = nv ? val*scl : 0.0f;
    }
}

// ---------------- remap + dedup (hash; representative = min original index) ------
__global__ void zRemapHash(const int* __restrict__ sA, const int* __restrict__ dA){
    int e = blockIdx.x*blockDim.x + threadIdx.x;
    if(e >= Ee) return;
    int ns = g_cmap[sA[e]];
    int nd = g_cmap[dA[e]];
    g_ns[e] = ns; g_nd[e] = nd;
    unsigned key = (unsigned)ns*60000u + (unsigned)nd;
    unsigned h = (key*2654435761u) & TABM;
    while(true){
        unsigned old = atomicCAS(&g_hkey[h], 0xFFFFFFFFu, key);
        if(old == 0xFFFFFFFFu || old == key){
            atomicMin(&g_hval[h], (unsigned)e);
            break;
        }
        h = (h + 1u) & TABM;
    }
}

// dedup + layer-2 degree counting fused
__global__ void zDedup(){
    int e = blockIdx.x*blockDim.x + threadIdx.x;
    if(e >= Ee) return;
    int ns = g_ns[e], nd = g_nd[e];
    unsigned key = (unsigned)ns*60000u + (unsigned)nd;
    unsigned h = (key*2654435761u) & TABM;
    while(g_hkey[h] != key) h = (h + 1u) & TABM;
    unsigned char ev = (g_hval[h] == (unsigned)e) ? 1 : 0;
    g_ev1[e] = ev;
    if(ev){
        atomicAdd(&g_degI[nd], 1);
        if(ns == nd) g_hasloop[nd] = 1;
    }
}

// ---------------- final pooling + log_softmax ----------------
__global__ void zPoolBatch(const int* __restrict__ batch, const float* __restrict__ x2){
    __shared__ float sc[Bb];
    __shared__ float ss[Bb*Cc];
    int t = threadIdx.x;
    if(t < Bb)    sc[t] = 0.f;
    if(t < Bb*Cc) ss[t] = 0.f;
    __syncthreads();
    for(int v = blockIdx.x*blockDim.x + t; v < Nn; v += gridDim.x*blockDim.x){
        if(g_nv2[v]){
            int b = batch[v];
            atomicAdd(&sc[b], 1.0f);
            #pragma unroll
            for(int c = 0; c < Cc; c++)
                atomicAdd(&ss[b*Cc + c], x2[(size_t)v*Cc + c]);
        }
    }
    __syncthreads();
    if(t < Bb)    atomicAdd(&g_cnt[t], sc[t]);
    if(t < Bb*Cc) atomicAdd(&g_sum[t], ss[t]);
}

__global__ void zFinal(float* __restrict__ out){
    __shared__ float gs[Bb*Cc];
    __shared__ float lse[Bb];
    int t = threadIdx.x;
    if(t < Bb*Cc) gs[t] = g_sum[t]/g_cnt[t/Cc];
    __syncthreads();
    if(t < Bb){
        float m = -1e30f;
        for(int c = 0; c < Cc; c++) m = fmaxf(m, gs[t*Cc + c]);
        float s = 0.f;
        for(int c = 0; c < Cc; c++) s += expf(gs[t*Cc + c] - m);
        lse[t] = m + logf(s);
    }
    __syncthreads();
    if(t < Bb*Cc) out[t] = gs[t] - lse[t/Cc];
}

// ---------------- launch ----------------
extern "C" void kernel_launch(void* const* d_in, const int* in_sizes, int n_in,
                              void* d_out, int out_size){
    (void)in_sizes; (void)n_in; (void)out_size;
    const float* x    = (const float*)d_in[0];
    const int*   src  = (const int*)  d_in[1];
    const int*   dst  = (const int*)  d_in[2];
    const int*   bat  = (const int*)  d_in[3];
    const float* W1   = (const float*)d_in[4];
    const float* b1   = (const float*)d_in[5];
    const float* W2   = (const float*)d_in[6];
    const float* b2   = (const float*)d_in[7];
    const float* Wp1  = (const float*)d_in[8];
    const float* bp1  = (const float*)d_in[9];
    const float* Wp2  = (const float*)d_in[10];
    const float* bp2  = (const float*)d_in[11];
    float* out = (float*)d_out;

    const int EB  = (Ee + NT - 1)/NT;
    const int NBn = (Nn + NT - 1)/NT;
    const int IB  = (int)((TAB + NT - 1)/NT);

    // every device-global pointer passed as a kernel ARG must come from
    // cudaGetSymbolAddress (host symbol == host shadow under ATS!)
    float *pT1, *pAcc1, *pH1, *pX1, *pT2, *pAcc2, *pH2, *pX2;
    cudaGetSymbolAddress((void**)&pT1,   g_t1);
    cudaGetSymbolAddress((void**)&pAcc1, g_acc1);
    cudaGetSymbolAddress((void**)&pH1,   g_h1);
    cudaGetSymbolAddress((void**)&pX1,   g_x1);
    cudaGetSymbolAddress((void**)&pT2,   g_t2);
    cudaGetSymbolAddress((void**)&pAcc2, g_acc2);
    cudaGetSymbolAddress((void**)&pH2,   g_h2);
    cudaGetSymbolAddress((void**)&pX2,   g_x2);
    int *pNs, *pNd;
    cudaGetSymbolAddress((void**)&pNs, g_ns);
    cudaGetSymbolAddress((void**)&pNd, g_nd);
    unsigned char *pEv1, *pNv0, *pNv1, *pNv2;
    cudaGetSymbolAddress((void**)&pEv1, g_ev1);
    cudaGetSymbolAddress((void**)&pNv0, g_nv0);
    cudaGetSymbolAddress((void**)&pNv1, g_nv1);
    cudaGetSymbolAddress((void**)&pNv2, g_nv2);

    zInitMain<<<IB, NT>>>();

    // ---- GCN layer 1 + relu ----
    zGemm1<<<Nn/8, NT>>>(x, W1, pT1);
    zDeg<<<EB, NT>>>(src, dst);
    zDinv<<<NBn, NT>>>(pNv0);
    zAgg<Hh><<<EB, NT>>>(src, dst, nullptr, pT1, pAcc1);
    zFinishGcn<Hh, true><<<NBn, NT>>>(pAcc1, pT1, b1, pH1);

    // ---- EdgePool 1 ----
    zRawMax<Hh><<<EB, NT>>>(pH1, src, dst, nullptr, Wp1, bp1);
    zNodePrep<<<NBn, NT>>>(pNv0);
    zEx<<<EB, NT>>>(dst, nullptr);
    zScore<<<EB, NT>>>(src, dst, nullptr);
    zMatch<<<148, NT>>>(src, dst);
    zPoolNode<Hh><<<NBn, NT>>>(pH1, pX1, pNv0, pNv1);

    // ---- remap + dedup (+ layer-2 degrees) ----
    zInit2<<<NBn, NT>>>();
    zRemapHash<<<EB, NT>>>(src, dst);
    zDedup<<<EB, NT>>>();

    // ---- GCN layer 2 (dinv fused with gemm2) ----
    zDinvGemm2<<<NBn, NT>>>(pNv1, pX1, W2, pT2);
    zAgg<Cc><<<EB, NT>>>(pNs, pNd, pEv1, pT2, pAcc2);
    zFinishGcn<Cc, false><<<NBn, NT>>>(pAcc2, pT2, b2, pH2);

    // ---- EdgePool 2 ----
    zRawMax<Cc><<<EB, NT>>>(pH2, pNs, pNd, pEv1, Wp2, bp2);
    zNodePrep<<<NBn, NT>>>(pNv1);
    zEx<<<EB, NT>>>(pNd, pEv1);
    zScore<<<EB, NT>>>(pNs, pNd, pEv1);
    zMatch<<<148, NT>>>(pNs, pNd);
    zPoolNode<Cc><<<NBn, NT>>>(pH2, pX2, pNv1, pNv2);

    // ---- mean pool + log_softmax ----
    zPoolBatch<<<NBn, NT>>>(bat, pX2);
    zFinal<<<1, 128>>>(out);
}

// round 13
// speedup vs baseline: 1.0672x; 1.0672x over previous
// GCN + EdgePool forward — R13: packed (prio,s,d) frontier lists + DEAD-sentinel
// best buffers (no alive[] array); zInit2 fused into zPoolNode<Hh>.
#include <cuda_runtime.h>
#include <math.h>

#define Nn 60000
#define Ee 600000
#define Ff 384
#define Hh 6
#define Cc 10
#define Bb 8
#define TAB (1u<<21)
#define TABM (TAB-1u)
#define NT 256
#define DEADP 0xFFFFFFFFFFFFFFFFull

// ---------------- scratch (static device globals; no allocation) ----------------
__device__ float g_t1[Nn*Hh];
__device__ float g_acc1[Nn*Hh];
__device__ float g_h1[Nn*Hh];
__device__ float g_x1[Nn*Hh];
__device__ float g_t2[Nn*Cc];
__device__ float g_acc2[Nn*Cc];
__device__ float g_h2[Nn*Cc];
__device__ float g_x2[Nn*Cc];

__device__ int   g_degI[Nn];
__device__ int   g_hasloop[Nn];
__device__ unsigned char g_addloop[Nn];
__device__ float g_dinv[Nn];

__device__ unsigned g_m[Nn];
__device__ float g_mf[Nn];
__device__ float g_s[Nn];
__device__ float g_raw[Ee];
__device__ float g_ex[Ee];
__device__ float g_score[Ee];

__device__ unsigned long long g_best[3][Nn];
__device__ unsigned long long g_listP[2][Ee];   // priority
__device__ unsigned long long g_listSD[2][Ee];  // (s<<32)|d
__device__ int   g_cntL[3];
__device__ int   g_partner[Nn];
__device__ float g_scale[Nn];
__device__ unsigned char g_dead[Nn];
__device__ int   g_cmapSrc[Nn];
__device__ int   g_cmap[Nn];
__device__ int   g_ns[Ee];
__device__ int   g_nd[Ee];
__device__ unsigned char g_ev1[Ee];
__device__ unsigned char g_nv0[Nn];
__device__ unsigned char g_nv1[Nn];
__device__ unsigned char g_nv2[Nn];

__device__ unsigned g_hkey[TAB];
__device__ unsigned g_hval[TAB];

__device__ float g_cnt[Bb];
__device__ float g_sum[Bb*Cc];

__device__ unsigned g_barCount;
__device__ volatile unsigned g_barGen;

// ---------------- helpers ----------------
__device__ __forceinline__ unsigned fkey(float f){
    unsigned b = __float_as_uint(f);
    return b ^ (((int)b >> 31) ? 0xFFFFFFFFu : 0x80000000u);
}
__device__ __forceinline__ float finv(unsigned k){
    unsigned b = (k & 0x80000000u) ? (k ^ 0x80000000u) : ~k;
    return __uint_as_float(b);
}

// ---------------- init ----------------
__global__ void zInitMain(){
    int stride = gridDim.x*blockDim.x;
    for(unsigned i = blockIdx.x*blockDim.x + threadIdx.x; i < TAB; i += stride){
        g_hkey[i] = 0xFFFFFFFFu; g_hval[i] = 0xFFFFFFFFu;
        if(i < Nn*Cc) g_acc2[i] = 0.f;
        if(i < Nn*Hh) g_acc1[i] = 0.f;
        if(i < Nn){ g_degI[i]=0; g_hasloop[i]=0; g_m[i]=0u; g_s[i]=0.f; g_nv0[i]=1; }
        if(i < Bb)    g_cnt[i]=0.f;
        if(i < Bb*Cc) g_sum[i]=0.f;
        if(i == 0){ g_barCount = 0u; }
    }
}

// ---------------- GEMM1: t1 = x @ W1  (60000x384 @ 384x6, exact fp32) ----------
__global__ void zGemm1(const float* __restrict__ x, const float* __restrict__ W1,
                       float* __restrict__ t1){
    __shared__ float Ws[Ff*Hh];
    for(int i = threadIdx.x; i < Ff*Hh; i += blockDim.x) Ws[i] = W1[i];
    __syncthreads();
    int warp = threadIdx.x >> 5, lane = threadIdx.x & 31;
    int row = blockIdx.x*8 + warp;
    if(row >= Nn) return;
    const float* xr = x + (size_t)row*Ff;
    float a0=0,a1=0,a2=0,a3=0,a4=0,a5=0;
    for(int k = lane; k < Ff; k += 32){
        float xv = xr[k];
        const float* w = Ws + k*Hh;
        a0 += xv*w[0]; a1 += xv*w[1]; a2 += xv*w[2];
        a3 += xv*w[3]; a4 += xv*w[4]; a5 += xv*w[5];
    }
    #pragma unroll
    for(int off = 16; off; off >>= 1){
        a0 += __shfl_down_sync(0xffffffffu, a0, off);
        a1 += __shfl_down_sync(0xffffffffu, a1, off);
        a2 += __shfl_down_sync(0xffffffffu, a2, off);
        a3 += __shfl_down_sync(0xffffffffu, a3, off);
        a4 += __shfl_down_sync(0xffffffffu, a4, off);
        a5 += __shfl_down_sync(0xffffffffu, a5, off);
    }
    if(lane == 0){
        float* o = t1 + (size_t)row*Hh;
        o[0]=a0; o[1]=a1; o[2]=a2; o[3]=a3; o[4]=a4; o[5]=a5;
    }
}

// ---------------- layer-2 fused: dinv + t2 = x1 @ W2 ---------------------------
__global__ void zDinvGemm2(const unsigned char* __restrict__ nv,
                           const float* __restrict__ x1, const float* __restrict__ W2,
                           float* __restrict__ t2){
    int v = blockIdx.x*blockDim.x + threadIdx.x;
    if(v >= Nn) return;
    int add = (nv[v] && !g_hasloop[v]) ? 1 : 0;
    g_addloop[v] = (unsigned char)add;
    int dg = g_degI[v] + add;
    g_dinv[v] = (dg > 0) ? 1.0f/sqrtf((float)dg) : 0.0f;
    float xr[Hh];
    #pragma unroll
    for(int j = 0; j < Hh; j++) xr[j] = x1[v*Hh + j];
    #pragma unroll
    for(int c = 0; c < Cc; c++){
        float a = 0.f;
        #pragma unroll
        for(int j = 0; j < Hh; j++) a += xr[j]*W2[j*Cc + c];
        t2[v*Cc + c] = a;
    }
}

// ---------------- degree / dinv ----------------
__global__ void zDeg(const int* __restrict__ sA, const int* __restrict__ dA){
    int e = blockIdx.x*blockDim.x + threadIdx.x;
    if(e >= Ee) return;
    int d = dA[e];
    atomicAdd(&g_degI[d], 1);
    if(sA[e] == d) g_hasloop[d] = 1;
}

__global__ void zDinv(const unsigned char* __restrict__ nv){
    int v = blockIdx.x*blockDim.x + threadIdx.x;
    if(v >= Nn) return;
    int add = (nv[v] && !g_hasloop[v]) ? 1 : 0;
    g_addloop[v] = (unsigned char)add;
    int dg = g_degI[v] + add;
    g_dinv[v] = (dg > 0) ? 1.0f/sqrtf((float)dg) : 0.0f;
}

template<int FD>
__global__ void zAgg(const int* __restrict__ sA, const int* __restrict__ dA,
                     const unsigned char* __restrict__ ev,
                     const float* __restrict__ t, float* __restrict__ acc){
    int e = blockIdx.x*blockDim.x + threadIdx.x;
    if(e >= Ee) return;
    if(ev && !ev[e]) return;
    int s = sA[e], d = dA[e];
    float c = g_dinv[s]*g_dinv[d];
    #pragma unroll
    for(int j = 0; j < FD; j++)
        atomicAdd(&acc[(size_t)d*FD + j], t[(size_t)s*FD + j]*c);
}

template<int FD, bool RELU>
__global__ void zFinishGcn(const float* __restrict__ acc, const float* __restrict__ t,
                           const float* __restrict__ bias, float* __restrict__ out){
    int v = blockIdx.x*blockDim.x + threadIdx.x;
    if(v >= Nn) return;
    float di = g_dinv[v];
    float al = g_addloop[v] ? di*di : 0.0f;
    #pragma unroll
    for(int j = 0; j < FD; j++){
        float o = acc[(size_t)v*FD + j] + al*t[(size_t)v*FD + j] + bias[j];
        out[(size_t)v*FD + j] = RELU ? fmaxf(o, 0.0f) : o;
    }
}

// ---------------- edge pool: score pipeline ----------------
template<int FD>
__global__ void zRawMax(const float* __restrict__ xf, const int* __restrict__ sA,
                        const int* __restrict__ dA, const unsigned char* __restrict__ ev,
                        const float* __restrict__ Wp, const float* __restrict__ bp){
    int e = blockIdx.x*blockDim.x + threadIdx.x;
    if(e >= Ee) return;
    int s = sA[e], d = dA[e];
    float r = bp[0];
    #pragma unroll
    for(int j = 0; j < FD; j++) r += xf[(size_t)s*FD + j]*Wp[j];
    #pragma unroll
    for(int j = 0; j < FD; j++) r += xf[(size_t)d*FD + j]*Wp[FD + j];
    g_raw[e] = r;
    bool valid = ev ? (ev[e] != 0) : true;
    if(valid) atomicMax(&g_m[d], fkey(r));
}

// fused: mf finalize + pool state init + best[0..1]/counters reset
__global__ void zNodePrep(const unsigned char* __restrict__ nv){
    int v = blockIdx.x*blockDim.x + threadIdx.x;
    if(v >= Nn) return;
    (void)nv;
    unsigned k = g_m[v];
    g_mf[v] = (k == 0u) ? 0.0f : finv(k);
    g_partner[v] = -1;
    g_scale[v]   = 1.0f;
    g_dead[v]    = 0;
    g_cmapSrc[v] = -1;
    g_best[0][v] = 0ull;
    g_best[1][v] = 0ull;
    if(v == 0){ g_cntL[0] = 0; g_cntL[1] = 0; g_cntL[2] = 0; }
}

__global__ void zEx(const int* __restrict__ dA, const unsigned char* __restrict__ ev){
    int e = blockIdx.x*blockDim.x + threadIdx.x;
    if(e >= Ee) return;
    bool valid = ev ? (ev[e] != 0) : true;
    float exv = 0.0f;
    if(valid){
        int d = dA[e];
        exv = expf(g_raw[e] - g_mf[d]);
        atomicAdd(&g_s[d], exv);
    }
    g_ex[e] = exv;
}

// score + initial packed list + round-0 priority posting
// NOTE: only valid+alive-capable edges enter; invalid (ev=0) edges never do.
__global__ void zScore(const int* __restrict__ sA, const int* __restrict__ dA,
                       const unsigned char* __restrict__ ev){
    int e = blockIdx.x*blockDim.x + threadIdx.x;
    if(e >= Ee) return;
    bool valid = ev ? (ev[e] != 0) : true;
    unsigned long long p = 0ull;
    int s = 0, d = 0;
    if(valid){
        s = sA[e]; d = dA[e];
        float sv = g_s[d];
        float sc = g_ex[e]/((sv > 0.f) ? sv : 1.f) + 0.5f;
        g_score[e] = sc;
        // total priority = (score desc, edge index asc) == stable argsort(-score)
        p = ((unsigned long long)fkey(sc) << 32)
          | (unsigned long long)(0xFFFFFFFFu - (unsigned)e);
        atomicMax(&g_best[0][s], p);
        atomicMax(&g_best[0][d], p);
    }
    unsigned mask = __ballot_sync(0xffffffffu, valid);   // Ee % 32 == 0: full warps
    if(valid){
        int lane = threadIdx.x & 31;
        int leader = __ffs(mask) - 1;
        int base = 0;
        if(lane == leader) base = atomicAdd(&g_cntL[0], __popc(mask));
        base = __shfl_sync(mask, base, leader);
        int idx = base + __popc(mask & ((1u << lane) - 1u));
        g_listP[0][idx]  = p;
        g_listSD[0][idx] = ((unsigned long long)(unsigned)s << 32) | (unsigned)d;
    }
}

// ---------------- persistent matching (locally-dominant == sequential greedy) ----
__device__ __forceinline__ void gbar(){
    __syncthreads();
    if(threadIdx.x == 0){
        __threadfence();
        unsigned gen = g_barGen;
        if(atomicAdd(&g_barCount, 1u) == gridDim.x - 1u){
            g_barCount = 0u;
            __threadfence();
            g_barGen = gen + 1u;
        } else {
            while(g_barGen == gen){ __nanosleep(64); }
            __threadfence();
        }
    }
    __syncthreads();
}

// on-chosen pool apply (arrays read only after kernel end)
__device__ __forceinline__ void applyChosen(unsigned long long p, int s, int d){
    int e = (int)(0xFFFFFFFFu - (unsigned)(p & 0xFFFFFFFFull));
    g_scale[s] = g_score[e];
    if(s != d){
        g_partner[s] = d;
        g_dead[d] = 1;
        g_cmapSrc[d] = s;
    }
}

// One sweep + ONE grid barrier per round; 3-buffer rotation; DEAD sentinel
// marks matched nodes inside the best buffers (no alive[] array).
__global__ void zMatch(){
    const int gid = blockIdx.x*blockDim.x + threadIdx.x;
    const int gsz = gridDim.x*blockDim.x;
    const int lane = threadIdx.x & 31;
    int rb = 0;    // read-buffer / counter index
    int cur = 0;   // list ping-pong
    for(int round = 0; round < 100000; round++){
        int n = *((volatile int*)&g_cntL[rb]);
        if(n == 0) break;
        int pb = rb + 1; if(pb == 3) pb = 0;
        int zb = pb + 1; if(zb == 3) zb = 0;
        volatile unsigned long long* bestR = (volatile unsigned long long*)g_best[rb];
        unsigned long long* bestP = g_best[pb];
        unsigned long long* bestZ = g_best[zb];
        volatile const unsigned long long* vlp  = (volatile const unsigned long long*)g_listP[cur];
        volatile const unsigned long long* vlsd = (volatile const unsigned long long*)g_listSD[cur];
        unsigned long long* onp  = g_listP[cur^1];
        unsigned long long* onsd = g_listSD[cur^1];
        // reset round-after-next buffer + counter (endpoint-only when small)
        if(2*n >= Nn){
            for(int v = gid; v < Nn; v += gsz) bestZ[v] = 0ull;
        } else {
            for(int i = gid; i < n; i += gsz){
                unsigned long long sd = vlsd[i];
                bestZ[(int)(sd >> 32)] = 0ull;
                bestZ[(int)(sd & 0xFFFFFFFFull)] = 0ull;
            }
        }
        if(gid == 0) g_cntL[zb] = 0;
        // fused choose + survivor-post sweep
        for(int i = gid; i < n; i += gsz){
            unsigned long long p  = vlp[i];
            unsigned long long sd = vlsd[i];
            int s = (int)(sd >> 32);
            int d = (int)(sd & 0xFFFFFFFFull);
            unsigned long long bs = bestR[s];
            unsigned long long bd = bestR[d];
            bool keep = false;
            if(bs != DEADP && bd != DEADP){
                if(bs == p && bd == p){
                    applyChosen(p, s, d);
                    atomicMax(&bestP[s], DEADP);
                    atomicMax(&bestP[d], DEADP);
                } else keep = true;
            }
            unsigned act = __activemask();
            unsigned mask = __ballot_sync(act, keep);
            if(keep){
                atomicMax(&bestP[s], p);
                atomicMax(&bestP[d], p);
                int leader = __ffs(mask) - 1;
                int base = 0;
                if(lane == leader) base = atomicAdd(&g_cntL[pb], __popc(mask));
                base = __shfl_sync(mask, base, leader);
                int idx = base + __popc(mask & ((1u << lane) - 1u));
                onp[idx]  = p;
                onsd[idx] = sd;
            }
        }
        gbar();
        rb = pb; cur ^= 1;
    }
}

// layer-1 pool node + layer-2 per-node resets (zInit2 fused)
template<int FD, bool RESET2>
__global__ void zPoolNode(const float* __restrict__ xin, float* __restrict__ xout,
                          const unsigned char* __restrict__ nvin, unsigned char* __restrict__ nvout){
    int v = blockIdx.x*blockDim.x + threadIdx.x;
    if(v >= Nn) return;
    unsigned char nv = (nvin[v] && !g_dead[v]) ? 1 : 0;
    nvout[v] = nv;
    int cs = g_cmapSrc[v];
    g_cmap[v] = (cs >= 0) ? cs : v;
    float scl = g_scale[v];
    int p = g_partner[v];
    #pragma unroll
    for(int j = 0; j < FD; j++){
        float val = xin[(size_t)v*FD + j] + ((p >= 0) ? xin[(size_t)p*FD + j] : 0.0f);
        xout[(size_t)v*FD + j] = nv ? val*scl : 0.0f;
    }
    if(RESET2){
        g_degI[v] = 0; g_hasloop[v] = 0; g_m[v] = 0u; g_s[v] = 0.f;
    }
}

// ---------------- remap + dedup (hash; representative = min original index) ------
__global__ void zRemapHash(const int* __restrict__ sA, const int* __restrict__ dA){
    int e = blockIdx.x*blockDim.x + threadIdx.x;
    if(e >= Ee) return;
    int ns = g_cmap[sA[e]];
    int nd = g_cmap[dA[e]];
    g_ns[e] = ns; g_nd[e] = nd;
    unsigned key = (unsigned)ns*60000u + (unsigned)nd;
    unsigned h = (key*2654435761u) & TABM;
    while(true){
        unsigned old = atomicCAS(&g_hkey[h], 0xFFFFFFFFu, key);
        if(old == 0xFFFFFFFFu || old == key){
            atomicMin(&g_hval[h], (unsigned)e);
            break;
        }
        h = (h + 1u) & TABM;
    }
}

// dedup + layer-2 degree counting fused
__global__ void zDedup(){
    int e = blockIdx.x*blockDim.x + threadIdx.x;
    if(e >= Ee) return;
    int ns = g_ns[e], nd = g_nd[e];
    unsigned key = (unsigned)ns*60000u + (unsigned)nd;
    unsigned h = (key*2654435761u) & TABM;
    while(g_hkey[h] != key) h = (h + 1u) & TABM;
    unsigned char ev = (g_hval[h] == (unsigned)e) ? 1 : 0;
    g_ev1[e] = ev;
    if(ev){
        atomicAdd(&g_degI[nd], 1);
        if(ns == nd) g_hasloop[nd] = 1;
    }
}

// ---------------- final pooling + log_softmax ----------------
__global__ void zPoolBatch(const int* __restrict__ batch, const float* __restrict__ x2){
    __shared__ float sc[Bb];
    __shared__ float ss[Bb*Cc];
    int t = threadIdx.x;
    if(t < Bb)    sc[t] = 0.f;
    if(t < Bb*Cc) ss[t] = 0.f;
    __syncthreads();
    for(int v = blockIdx.x*blockDim.x + t; v < Nn; v += gridDim.x*blockDim.x){
        if(g_nv2[v]){
            int b = batch[v];
            atomicAdd(&sc[b], 1.0f);
            #pragma unroll
            for(int c = 0; c < Cc; c++)
                atomicAdd(&ss[b*Cc + c], x2[(size_t)v*Cc + c]);
        }
    }
    __syncthreads();
    if(t < Bb)    atomicAdd(&g_cnt[t], sc[t]);
    if(t < Bb*Cc) atomicAdd(&g_sum[t], ss[t]);
}

__global__ void zFinal(float* __restrict__ out){
    __shared__ float gs[Bb*Cc];
    __shared__ float lse[Bb];
    int t = threadIdx.x;
    if(t < Bb*Cc) gs[t] = g_sum[t]/g_cnt[t/Cc];
    __syncthreads();
    if(t < Bb){
        float m = -1e30f;
        for(int c = 0; c < Cc; c++) m = fmaxf(m, gs[t*Cc + c]);
        float s = 0.f;
        for(int c = 0; c < Cc; c++) s += expf(gs[t*Cc + c] - m);
        lse[t] = m + logf(s);
    }
    __syncthreads();
    if(t < Bb*Cc) out[t] = gs[t] - lse[t/Cc];
}

// ---------------- launch ----------------
extern "C" void kernel_launch(void* const* d_in, const int* in_sizes, int n_in,
                              void* d_out, int out_size){
    (void)in_sizes; (void)n_in; (void)out_size;
    const float* x    = (const float*)d_in[0];
    const int*   src  = (const int*)  d_in[1];
    const int*   dst  = (const int*)  d_in[2];
    const int*   bat  = (const int*)  d_in[3];
    const float* W1   = (const float*)d_in[4];
    const float* b1   = (const float*)d_in[5];
    const float* W2   = (const float*)d_in[6];
    const float* b2   = (const float*)d_in[7];
    const float* Wp1  = (const float*)d_in[8];
    const float* bp1  = (const float*)d_in[9];
    const float* Wp2  = (const float*)d_in[10];
    const float* bp2  = (const float*)d_in[11];
    float* out = (float*)d_out;

    const int EB  = (Ee + NT - 1)/NT;
    const int NBn = (Nn + NT - 1)/NT;
    const int IB  = (int)((TAB + NT - 1)/NT);

    // every device-global pointer passed as a kernel ARG must come from
    // cudaGetSymbolAddress (host symbol == host shadow under ATS!)
    float *pT1, *pAcc1, *pH1, *pX1, *pT2, *pAcc2, *pH2, *pX2;
    cudaGetSymbolAddress((void**)&pT1,   g_t1);
    cudaGetSymbolAddress((void**)&pAcc1, g_acc1);
    cudaGetSymbolAddress((void**)&pH1,   g_h1);
    cudaGetSymbolAddress((void**)&pX1,   g_x1);
    cudaGetSymbolAddress((void**)&pT2,   g_t2);
    cudaGetSymbolAddress((void**)&pAcc2, g_acc2);
    cudaGetSymbolAddress((void**)&pH2,   g_h2);
    cudaGetSymbolAddress((void**)&pX2,   g_x2);
    int *pNs, *pNd;
    cudaGetSymbolAddress((void**)&pNs, g_ns);
    cudaGetSymbolAddress((void**)&pNd, g_nd);
    unsigned char *pEv1, *pNv0, *pNv1, *pNv2;
    cudaGetSymbolAddress((void**)&pEv1, g_ev1);
    cudaGetSymbolAddress((void**)&pNv0, g_nv0);
    cudaGetSymbolAddress((void**)&pNv1, g_nv1);
    cudaGetSymbolAddress((void**)&pNv2, g_nv2);

    zInitMain<<<IB, NT>>>();

    // ---- GCN layer 1 + relu ----
    zGemm1<<<Nn/8, NT>>>(x, W1, pT1);
    zDeg<<<EB, NT>>>(src, dst);
    zDinv<<<NBn, NT>>>(pNv0);
    zAgg<Hh><<<EB, NT>>>(src, dst, nullptr, pT1, pAcc1);
    zFinishGcn<Hh, true><<<NBn, NT>>>(pAcc1, pT1, b1, pH1);

    // ---- EdgePool 1 ----
    zRawMax<Hh><<<EB, NT>>>(pH1, src, dst, nullptr, Wp1, bp1);
    zNodePrep<<<NBn, NT>>>(pNv0);
    zEx<<<EB, NT>>>(dst, nullptr);
    zScore<<<EB, NT>>>(src, dst, nullptr);
    zMatch<<<148, NT>>>();
    zPoolNode<Hh, true><<<NBn, NT>>>(pH1, pX1, pNv0, pNv1);

    // ---- remap + dedup (+ layer-2 degrees) ----
    zRemapHash<<<EB, NT>>>(src, dst);
    zDedup<<<EB, NT>>>();

    // ---- GCN layer 2 (dinv fused with gemm2) ----
    zDinvGemm2<<<NBn, NT>>>(pNv1, pX1, W2, pT2);
    zAgg<Cc><<<EB, NT>>>(pNs, pNd, pEv1, pT2, pAcc2);
    zFinishGcn<Cc, false><<<NBn, NT>>>(pAcc2, pT2, b2, pH2);

    // ---- EdgePool 2 ----
    zRawMax<Cc><<<EB, NT>>>(pH2, pNs, pNd, pEv1, Wp2, bp2);
    zNodePrep<<<NBn, NT>>>(pNv1);
    zEx<<<EB, NT>>>(pNd, pEv1);
    zScore<<<EB, NT>>>(pNs, pNd, pEv1);
    zMatch<<<148, NT>>>();
    zPoolNode<Cc, false><<<NBn, NT>>>(pH2, pX2, pNv1, pNv2);

    // ---- mean pool + log_softmax ----
    zPoolBatch<<<NBn, NT>>>(bat, pX2);
    zFinal<<<1, 128>>>(out);
}

// round 14
// speedup vs baseline: 1.0999x; 1.0307x over previous
// GCN + EdgePool forward — R14: softmax max-pass eliminated (2-pass score),
// 4-buffer zMatch with reset hidden inside the grid barrier, prep fused away.
#include <cuda_runtime.h>
#include <math.h>

#define Nn 60000
#define Ee 600000
#define Ff 384
#define Hh 6
#define Cc 10
#define Bb 8
#define TAB (1u<<21)
#define TABM (TAB-1u)
#define NT 256
#define DEADP 0xFFFFFFFFFFFFFFFFull

// ---------------- scratch (static device globals; no allocation) ----------------
__device__ float g_t1[Nn*Hh];
__device__ float g_acc1[Nn*Hh];
__device__ float g_h1[Nn*Hh];
__device__ float g_x1[Nn*Hh];
__device__ float g_t2[Nn*Cc];
__device__ float g_acc2[Nn*Cc];
__device__ float g_h2[Nn*Cc];
__device__ float g_x2[Nn*Cc];

__device__ int   g_degI[Nn];
__device__ int   g_hasloop[Nn];
__device__ unsigned char g_addloop[Nn];
__device__ float g_dinv[Nn];

__device__ float g_s[Nn];
__device__ float g_ex[Ee];
__device__ float g_score[Ee];

__device__ unsigned long long g_best[4][Nn];
__device__ unsigned long long g_listP[2][Ee];   // priority
__device__ unsigned long long g_listSD[2][Ee];  // (s<<32)|d
__device__ int   g_cntL[4];
__device__ int   g_partner[Nn];
__device__ float g_scale[Nn];
__device__ unsigned char g_dead[Nn];
__device__ int   g_cmapSrc[Nn];
__device__ int   g_cmap[Nn];
__device__ int   g_ns[Ee];
__device__ int   g_nd[Ee];
__device__ unsigned char g_ev1[Ee];
__device__ unsigned char g_nv1[Nn];
__device__ unsigned char g_nv2[Nn];

__device__ unsigned g_hkey[TAB];
__device__ unsigned g_hval[TAB];

__device__ float g_cnt[Bb];
__device__ float g_sum[Bb*Cc];

__device__ unsigned g_barCount;
__device__ volatile unsigned g_barGen;

// ---------------- helpers ----------------
__device__ __forceinline__ unsigned fkey(float f){
    unsigned b = __float_as_uint(f);
    return b ^ (((int)b >> 31) ? 0xFFFFFFFFu : 0x80000000u);
}

// ---------------- init (also stage-1 matching prep) ----------------
__global__ void zInitMain(){
    int stride = gridDim.x*blockDim.x;
    for(unsigned i = blockIdx.x*blockDim.x + threadIdx.x; i < TAB; i += stride){
        g_hkey[i] = 0xFFFFFFFFu; g_hval[i] = 0xFFFFFFFFu;
        if(i < Nn*Cc) g_acc2[i] = 0.f;
        if(i < Nn*Hh) g_acc1[i] = 0.f;
        if(i < Nn){
            g_degI[i]=0; g_hasloop[i]=0; g_s[i]=0.f;
            g_partner[i] = -1; g_scale[i] = 1.0f; g_dead[i] = 0; g_cmapSrc[i] = -1;
            g_best[0][i] = 0ull; g_best[1][i] = 0ull; g_best[2][i] = 0ull;
        }
        if(i < Bb)    g_cnt[i]=0.f;
        if(i < Bb*Cc) g_sum[i]=0.f;
        if(i < 4)     g_cntL[i] = 0;
        if(i == 0)    g_barCount = 0u;
    }
}

// ---------------- GEMM1: t1 = x @ W1  (60000x384 @ 384x6, exact fp32) ----------
__global__ void zGemm1(const float* __restrict__ x, const float* __restrict__ W1,
                       float* __restrict__ t1){
    __shared__ float Ws[Ff*Hh];
    for(int i = threadIdx.x; i < Ff*Hh; i += blockDim.x) Ws[i] = W1[i];
    __syncthreads();
    int warp = threadIdx.x >> 5, lane = threadIdx.x & 31;
    int row = blockIdx.x*8 + warp;
    if(row >= Nn) return;
    const float* xr = x + (size_t)row*Ff;
    float a0=0,a1=0,a2=0,a3=0,a4=0,a5=0;
    for(int k = lane; k < Ff; k += 32){
        float xv = xr[k];
        const float* w = Ws + k*Hh;
        a0 += xv*w[0]; a1 += xv*w[1]; a2 += xv*w[2];
        a3 += xv*w[3]; a4 += xv*w[4]; a5 += xv*w[5];
    }
    #pragma unroll
    for(int off = 16; off; off >>= 1){
        a0 += __shfl_down_sync(0xffffffffu, a0, off);
        a1 += __shfl_down_sync(0xffffffffu, a1, off);
        a2 += __shfl_down_sync(0xffffffffu, a2, off);
        a3 += __shfl_down_sync(0xffffffffu, a3, off);
        a4 += __shfl_down_sync(0xffffffffu, a4, off);
        a5 += __shfl_down_sync(0xffffffffu, a5, off);
    }
    if(lane == 0){
        float* o = t1 + (size_t)row*Hh;
        o[0]=a0; o[1]=a1; o[2]=a2; o[3]=a3; o[4]=a4; o[5]=a5;
    }
}

// ---------------- layer-2 fused: dinv + t2 = x1 @ W2 ---------------------------
__global__ void zDinvGemm2(const unsigned char* __restrict__ nv,
                           const float* __restrict__ x1, const float* __restrict__ W2,
                           float* __restrict__ t2){
    int v = blockIdx.x*blockDim.x + threadIdx.x;
    if(v >= Nn) return;
    int add = (nv[v] && !g_hasloop[v]) ? 1 : 0;
    g_addloop[v] = (unsigned char)add;
    int dg = g_degI[v] + add;
    g_dinv[v] = (dg > 0) ? 1.0f/sqrtf((float)dg) : 0.0f;
    float xr[Hh];
    #pragma unroll
    for(int j = 0; j < Hh; j++) xr[j] = x1[v*Hh + j];
    #pragma unroll
    for(int c = 0; c < Cc; c++){
        float a = 0.f;
        #pragma unroll
        for(int j = 0; j < Hh; j++) a += xr[j]*W2[j*Cc + c];
        t2[v*Cc + c] = a;
    }
}

// ---------------- degree / dinv (stage 1: all nodes valid) ----------------
__global__ void zDeg(const int* __restrict__ sA, const int* __restrict__ dA){
    int e = blockIdx.x*blockDim.x + threadIdx.x;
    if(e >= Ee) return;
    int d = dA[e];
    atomicAdd(&g_degI[d], 1);
    if(sA[e] == d) g_hasloop[d] = 1;
}

__global__ void zDinv1(){
    int v = blockIdx.x*blockDim.x + threadIdx.x;
    if(v >= Nn) return;
    int add = g_hasloop[v] ? 0 : 1;
    g_addloop[v] = (unsigned char)add;
    int dg = g_degI[v] + add;
    g_dinv[v] = (dg > 0) ? 1.0f/sqrtf((float)dg) : 0.0f;
}

template<int FD>
__global__ void zAgg(const int* __restrict__ sA, const int* __restrict__ dA,
                     const unsigned char* __restrict__ ev,
                     const float* __restrict__ t, float* __restrict__ acc){
    int e = blockIdx.x*blockDim.x + threadIdx.x;
    if(e >= Ee) return;
    if(ev && !ev[e]) return;
    int s = sA[e], d = dA[e];
    float c = g_dinv[s]*g_dinv[d];
    #pragma unroll
    for(int j = 0; j < FD; j++)
        atomicAdd(&acc[(size_t)d*FD + j], t[(size_t)s*FD + j]*c);
}

template<int FD, bool RELU>
__global__ void zFinishGcn(const float* __restrict__ acc, const float* __restrict__ t,
                           const float* __restrict__ bias, float* __restrict__ out){
    int v = blockIdx.x*blockDim.x + threadIdx.x;
    if(v >= Nn) return;
    float di = g_dinv[v];
    float al = g_addloop[v] ? di*di : 0.0f;
    #pragma unroll
    for(int j = 0; j < FD; j++){
        float o = acc[(size_t)v*FD + j] + al*t[(size_t)v*FD + j] + bias[j];
        out[(size_t)v*FD + j] = RELU ? fmaxf(o, 0.0f) : o;
    }
}

// ---------------- edge pool pass 1: raw -> exp -> segment sum ----------------
// (softmax max-shift eliminated: score = ex/sum is invariant to it; raw is O(1))
template<int FD>
__global__ void zPass1(const float* __restrict__ xf, const int* __restrict__ sA,
                       const int* __restrict__ dA, const unsigned char* __restrict__ ev,
                       const float* __restrict__ Wp, const float* __restrict__ bp){
    int e = blockIdx.x*blockDim.x + threadIdx.x;
    if(e >= Ee) return;
    bool valid = ev ? (ev[e] != 0) : true;
    float exv = 0.0f;
    if(valid){
        int s = sA[e], d = dA[e];
        float r = bp[0];
        #pragma unroll
        for(int j = 0; j < FD; j++) r += xf[(size_t)s*FD + j]*Wp[j];
        #pragma unroll
        for(int j = 0; j < FD; j++) r += xf[(size_t)d*FD + j]*Wp[FD + j];
        exv = expf(r);
        atomicAdd(&g_s[d], exv);
    }
    g_ex[e] = exv;
}

// ---------------- pass 2: score + packed list + round-0 priority posting --------
__global__ void zPass2(const int* __restrict__ sA, const int* __restrict__ dA,
                       const unsigned char* __restrict__ ev){
    int e = blockIdx.x*blockDim.x + threadIdx.x;
    if(e >= Ee) return;
    bool valid = ev ? (ev[e] != 0) : true;
    unsigned long long p = 0ull;
    int s = 0, d = 0;
    if(valid){
        s = sA[e]; d = dA[e];
        float sv = g_s[d];
        float sc = g_ex[e]/((sv > 0.f) ? sv : 1.f) + 0.5f;
        g_score[e] = sc;
        // total priority = (score desc, edge index asc) == stable argsort(-score)
        p = ((unsigned long long)fkey(sc) << 32)
          | (unsigned long long)(0xFFFFFFFFu - (unsigned)e);
        atomicMax(&g_best[0][s], p);
        atomicMax(&g_best[0][d], p);
    }
    unsigned mask = __ballot_sync(0xffffffffu, valid);   // Ee % 32 == 0: full warps
    if(valid){
        int lane = threadIdx.x & 31;
        int leader = __ffs(mask) - 1;
        int base = 0;
        if(lane == leader) base = atomicAdd(&g_cntL[0], __popc(mask));
        base = __shfl_sync(mask, base, leader);
        int idx = base + __popc(mask & ((1u << lane) - 1u));
        g_listP[0][idx]  = p;
        g_listSD[0][idx] = ((unsigned long long)(unsigned)s << 32) | (unsigned)d;
    }
}

// on-chosen pool apply (arrays read only after kernel end)
__device__ __forceinline__ void applyChosen(unsigned long long p, int s, int d){
    int e = (int)(0xFFFFFFFFu - (unsigned)(p & 0xFFFFFFFFull));
    g_scale[s] = g_score[e];
    if(s != d){
        g_partner[s] = d;
        g_dead[d] = 1;
        g_cmapSrc[d] = s;
    }
}

// ---------------- persistent matching (locally-dominant == sequential greedy) ----
// Round r: read best[r%4], post best[(r+1)%4], and reset best[(r+3)%4] INSIDE the
// grid barrier (between arrive and wait) — that buffer is next posted in round
// r+2, which cannot start before this block arrives at barrier r+1 (post-reset).
__global__ void zMatch(){
    const int gid = blockIdx.x*blockDim.x + threadIdx.x;
    const int gsz = gridDim.x*blockDim.x;
    const int lane = threadIdx.x & 31;
    __shared__ unsigned sgen;
    int cur = 0;   // list ping-pong
    for(int round = 0; round < 100000; round++){
        int rb = round & 3;
        int n = *((volatile int*)&g_cntL[rb]);
        if(n == 0) break;
        int pb = (round + 1) & 3;
        int zb = (round + 3) & 3;
        volatile unsigned long long* bestR = (volatile unsigned long long*)g_best[rb];
        unsigned long long* bestP = g_best[pb];
        unsigned long long* bestZ = g_best[zb];
        volatile const unsigned long long* vlp  = (volatile const unsigned long long*)g_listP[cur];
        volatile const unsigned long long* vlsd = (volatile const unsigned long long*)g_listSD[cur];
        unsigned long long* onp  = g_listP[cur^1];
        unsigned long long* onsd = g_listSD[cur^1];
        // fused choose + survivor-post sweep
        for(int i = gid; i < n; i += gsz){
            unsigned long long p  = vlp[i];
            unsigned long long sd = vlsd[i];
            int s = (int)(sd >> 32);
            int d = (int)(sd & 0xFFFFFFFFull);
            unsigned long long bs = bestR[s];
            unsigned long long bd = bestR[d];
            bool keep = false;
            if(bs != DEADP && bd != DEADP){
                if(bs == p && bd == p){
                    applyChosen(p, s, d);
                    atomicMax(&bestP[s], DEADP);
                    atomicMax(&bestP[d], DEADP);
                } else keep = true;
            }
            unsigned act = __activemask();
            unsigned mask = __ballot_sync(act, keep);
            if(keep){
                atomicMax(&bestP[s], p);
                atomicMax(&bestP[d], p);
                int leader = __ffs(mask) - 1;
                int base = 0;
                if(lane == leader) base = atomicAdd(&g_cntL[pb], __popc(mask));
                base = __shfl_sync(mask, base, leader);
                int idx = base + __popc(mask & ((1u << lane) - 1u));
                onp[idx]  = p;
                onsd[idx] = sd;
            }
        }
        // barrier arrive
        __syncthreads();
        if(threadIdx.x == 0){
            __threadfence();
            unsigned gen = g_barGen;
            sgen = gen;
            if(atomicAdd(&g_barCount, 1u) == gridDim.x - 1u){
                g_barCount = 0u;
                __threadfence();
                g_barGen = gen + 1u;
            }
        }
        __syncthreads();
        // overlapped reset of best[(r+3)%4] + its counter
        if(2*n >= Nn){
            for(int v = gid; v < Nn; v += gsz) bestZ[v] = 0ull;
        } else {
            for(int i = gid; i < n; i += gsz){
                unsigned long long sd = vlsd[i];
                bestZ[(int)(sd >> 32)] = 0ull;
                bestZ[(int)(sd & 0xFFFFFFFFull)] = 0ull;
            }
        }
        if(gid == 0) g_cntL[zb] = 0;
        // barrier wait
        if(threadIdx.x == 0){
            while(g_barGen == sgen){ __nanosleep(64); }
            __threadfence();
        }
        __syncthreads();
        cur ^= 1;
    }
}

// pool node; HAVENV=false => all nodes valid (stage 1). RESET2 preps stage 2.
template<int FD, bool HAVENV, bool RESET2>
__global__ void zPoolNode(const float* __restrict__ xin, float* __restrict__ xout,
                          const unsigned char* __restrict__ nvin, unsigned char* __restrict__ nvout){
    int v = blockIdx.x*blockDim.x + threadIdx.x;
    if(v >= Nn) return;
    unsigned char nv = ((HAVENV ? (nvin[v] != 0) : true) && !g_dead[v]) ? 1 : 0;
    nvout[v] = nv;
    int cs = g_cmapSrc[v];
    g_cmap[v] = (cs >= 0) ? cs : v;
    float scl = g_scale[v];
    int p = g_partner[v];
    #pragma unroll
    for(int j = 0; j < FD; j++){
        float val = xin[(size_t)v*FD + j] + ((p >= 0) ? xin[(size_t)p*FD + j] : 0.0f);
        xout[(size_t)v*FD + j] = nv ? val*scl : 0.0f;
    }
    if(RESET2){
        g_degI[v] = 0; g_hasloop[v] = 0; g_s[v] = 0.f;
        g_partner[v] = -1; g_scale[v] = 1.0f; g_dead[v] = 0; g_cmapSrc[v] = -1;
        g_best[0][v] = 0ull; g_best[1][v] = 0ull; g_best[2][v] = 0ull;
        if(v < 4) g_cntL[v] = 0;
    }
}

// ---------------- remap + dedup (hash; representative = min original index) ------
__global__ void zRemapHash(const int* __restrict__ sA, const int* __restrict__ dA){
    int e = blockIdx.x*blockDim.x + threadIdx.x;
    if(e >= Ee) return;
    int ns = g_cmap[sA[e]];
    int nd = g_cmap[dA[e]];
    g_ns[e] = ns; g_nd[e] = nd;
    unsigned key = (unsigned)ns*60000u + (unsigned)nd;
    unsigned h = (key*2654435761u) & TABM;
    while(true){
        unsigned old = atomicCAS(&g_hkey[h], 0xFFFFFFFFu, key);
        if(old == 0xFFFFFFFFu || old == key){
            atomicMin(&g_hval[h], (unsigned)e);
            break;
        }
        h = (h + 1u) & TABM;
    }
}

// dedup + layer-2 degree counting fused
__global__ void zDedup(){
    int e = blockIdx.x*blockDim.x + threadIdx.x;
    if(e >= Ee) return;
    int ns = g_ns[e], nd = g_nd[e];
    unsigned key = (unsigned)ns*60000u + (unsigned)nd;
    unsigned h = (key*2654435761u) & TABM;
    while(g_hkey[h] != key) h = (h + 1u) & TABM;
    unsigned char ev = (g_hval[h] == (unsigned)e) ? 1 : 0;
    g_ev1[e] = ev;
    if(ev){
        atomicAdd(&g_degI[nd], 1);
        if(ns == nd) g_hasloop[nd] = 1;
    }
}

// ---------------- final pooling + log_softmax ----------------
__global__ void zPoolBatch(const int* __restrict__ batch, const float* __restrict__ x2){
    __shared__ float sc[Bb];
    __shared__ float ss[Bb*Cc];
    int t = threadIdx.x;
    if(t < Bb)    sc[t] = 0.f;
    if(t < Bb*Cc) ss[t] = 0.f;
    __syncthreads();
    for(int v = blockIdx.x*blockDim.x + t; v < Nn; v += gridDim.x*blockDim.x){
        if(g_nv2[v]){
            int b = batch[v];
            atomicAdd(&sc[b], 1.0f);
            #pragma unroll
            for(int c = 0; c < Cc; c++)
                atomicAdd(&ss[b*Cc + c], x2[(size_t)v*Cc + c]);
        }
    }
    __syncthreads();
    if(t < Bb)    atomicAdd(&g_cnt[t], sc[t]);
    if(t < Bb*Cc) atomicAdd(&g_sum[t], ss[t]);
}

__global__ void zFinal(float* __restrict__ out){
    __shared__ float gs[Bb*Cc];
    __shared__ float lse[Bb];
    int t = threadIdx.x;
    if(t < Bb*Cc) gs[t] = g_sum[t]/g_cnt[t/Cc];
    __syncthreads();
    if(t < Bb){
        float m = -1e30f;
        for(int c = 0; c < Cc; c++) m = fmaxf(m, gs[t*Cc + c]);
        float s = 0.f;
        for(int c = 0; c < Cc; c++) s += expf(gs[t*Cc + c] - m);
        lse[t] = m + logf(s);
    }
    __syncthreads();
    if(t < Bb*Cc) out[t] = gs[t] - lse[t/Cc];
}

// ---------------- launch ----------------
extern "C" void kernel_launch(void* const* d_in, const int* in_sizes, int n_in,
                              void* d_out, int out_size){
    (void)in_sizes; (void)n_in; (void)out_size;
    const float* x    = (const float*)d_in[0];
    const int*   src  = (const int*)  d_in[1];
    const int*   dst  = (const int*)  d_in[2];
    const int*   bat  = (const int*)  d_in[3];
    const float* W1   = (const float*)d_in[4];
    const float* b1   = (const float*)d_in[5];
    const float* W2   = (const float*)d_in[6];
    const float* b2   = (const float*)d_in[7];
    const float* Wp1  = (const float*)d_in[8];
    const float* bp1  = (const float*)d_in[9];
    const float* Wp2  = (const float*)d_in[10];
    const float* bp2  = (const float*)d_in[11];
    float* out = (float*)d_out;

    const int EB  = (Ee + NT - 1)/NT;
    const int NBn = (Nn + NT - 1)/NT;
    const int IB  = (int)((TAB + NT - 1)/NT);

    // every device-global pointer passed as a kernel ARG must come from
    // cudaGetSymbolAddress (host symbol == host shadow under ATS!)
    float *pT1, *pAcc1, *pH1, *pX1, *pT2, *pAcc2, *pH2, *pX2;
    cudaGetSymbolAddress((void**)&pT1,   g_t1);
    cudaGetSymbolAddress((void**)&pAcc1, g_acc1);
    cudaGetSymbolAddress((void**)&pH1,   g_h1);
    cudaGetSymbolAddress((void**)&pX1,   g_x1);
    cudaGetSymbolAddress((void**)&pT2,   g_t2);
    cudaGetSymbolAddress((void**)&pAcc2, g_acc2);
    cudaGetSymbolAddress((void**)&pH2,   g_h2);
    cudaGetSymbolAddress((void**)&pX2,   g_x2);
    int *pNs, *pNd;
    cudaGetSymbolAddress((void**)&pNs, g_ns);
    cudaGetSymbolAddress((void**)&pNd, g_nd);
    unsigned char *pEv1, *pNv1, *pNv2;
    cudaGetSymbolAddress((void**)&pEv1, g_ev1);
    cudaGetSymbolAddress((void**)&pNv1, g_nv1);
    cudaGetSymbolAddress((void**)&pNv2, g_nv2);

    zInitMain<<<IB, NT>>>();

    // ---- GCN layer 1 + relu ----
    zGemm1<<<Nn/8, NT>>>(x, W1, pT1);
    zDeg<<<EB, NT>>>(src, dst);
    zDinv1<<<NBn, NT>>>();
    zAgg<Hh><<<EB, NT>>>(src, dst, nullptr, pT1, pAcc1);
    zFinishGcn<Hh, true><<<NBn, NT>>>(pAcc1, pT1, b1, pH1);

    // ---- EdgePool 1 ----
    zPass1<Hh><<<EB, NT>>>(pH1, src, dst, nullptr, Wp1, bp1);
    zPass2<<<EB, NT>>>(src, dst, nullptr);
    zMatch<<<148, NT>>>();
    zPoolNode<Hh, false, true><<<NBn, NT>>>(pH1, pX1, nullptr, pNv1);

    // ---- remap + dedup (+ layer-2 degrees) ----
    zRemapHash<<<EB, NT>>>(src, dst);
    zDedup<<<EB, NT>>>();

    // ---- GCN layer 2 (dinv fused with gemm2) ----
    zDinvGemm2<<<NBn, NT>>>(pNv1, pX1, W2, pT2);
    zAgg<Cc><<<EB, NT>>>(pNs, pNd, pEv1, pT2, pAcc2);
    zFinishGcn<Cc, false><<<NBn, NT>>>(pAcc2, pT2, b2, pH2);

    // ---- EdgePool 2 ----
    zPass1<Cc><<<EB, NT>>>(pH2, pNs, pNd, pEv1, Wp2, bp2);
    zPass2<<<EB, NT>>>(pNs, pNd, pEv1);
    zMatch<<<148, NT>>>();
    zPoolNode<Cc, true, false><<<NBn, NT>>>(pH2, pX2, pNv1, pNv2);

    // ---- mean pool + log_softmax ----
    zPoolBatch<<<NBn, NT>>>(bat, pX2);
    zFinal<<<1, 128>>>(out);
}

// round 15
// speedup vs baseline: 1.1508x; 1.0463x over previous
// GCN + EdgePool forward — R15: Suitor matching (no rounds, no grid barriers),
// CSR adjacency built per stage; extraction fused into pool-node kernel.
#include <cuda_runtime.h>
#include <math.h>

#define Nn 60000
#define Ee 600000
#define AE (2*Ee)
#define Ff 384
#define Hh 6
#define Cc 10
#define Bb 8
#define TAB (1u<<21)
#define TABM (TAB-1u)
#define NT 256
#define NB ((Nn + NT - 1)/NT)

// ---------------- scratch (static device globals; no allocation) ----------------
__device__ float g_t1[Nn*Hh];
__device__ float g_acc1[Nn*Hh];
__device__ float g_h1[Nn*Hh];
__device__ float g_x1[Nn*Hh];
__device__ float g_t2[Nn*Cc];
__device__ float g_acc2[Nn*Cc];
__device__ float g_h2[Nn*Cc];
__device__ float g_x2[Nn*Cc];

__device__ int   g_degI[Nn];
__device__ int   g_hasloop[Nn];
__device__ unsigned char g_addloop[Nn];
__device__ float g_dinv[Nn];

__device__ float g_s[Nn];
__device__ float g_ex[Ee];
__device__ float g_score[Ee];

__device__ unsigned long long g_suitor[Nn];
__device__ int g_adjCnt[Nn];
__device__ int g_off[Nn+1];
__device__ int g_cur[Nn];
__device__ unsigned long long g_adjP[AE];
__device__ int g_adjO[AE];
__device__ int g_bsum[NT];

__device__ int   g_cmap[Nn];
__device__ int   g_ns[Ee];
__device__ int   g_nd[Ee];
__device__ unsigned char g_ev1[Ee];
__device__ unsigned char g_nv1[Nn];
__device__ unsigned char g_nv2[Nn];

__device__ unsigned g_hkey[TAB];
__device__ unsigned g_hval[TAB];

__device__ float g_cnt[Bb];
__device__ float g_sum[Bb*Cc];

// ---------------- helpers ----------------
__device__ __forceinline__ unsigned fkey(float f){
    unsigned b = __float_as_uint(f);
    return b ^ (((int)b >> 31) ? 0xFFFFFFFFu : 0x80000000u);
}

// ---------------- init ----------------
__global__ void zInitMain(){
    int stride = gridDim.x*blockDim.x;
    for(unsigned i = blockIdx.x*blockDim.x + threadIdx.x; i < TAB; i += stride){
        g_hkey[i] = 0xFFFFFFFFu; g_hval[i] = 0xFFFFFFFFu;
        if(i < Nn*Cc) g_acc2[i] = 0.f;
        if(i < Nn*Hh) g_acc1[i] = 0.f;
        if(i < Nn){
            g_degI[i]=0; g_hasloop[i]=0; g_s[i]=0.f;
            g_suitor[i]=0ull; g_adjCnt[i]=0;
        }
        if(i < Bb)    g_cnt[i]=0.f;
        if(i < Bb*Cc) g_sum[i]=0.f;
    }
}

// ---------------- GEMM1: t1 = x @ W1  (60000x384 @ 384x6, exact fp32) ----------
__global__ void zGemm1(const float* __restrict__ x, const float* __restrict__ W1,
                       float* __restrict__ t1){
    __shared__ float Ws[Ff*Hh];
    for(int i = threadIdx.x; i < Ff*Hh; i += blockDim.x) Ws[i] = W1[i];
    __syncthreads();
    int warp = threadIdx.x >> 5, lane = threadIdx.x & 31;
    int row = blockIdx.x*8 + warp;
    if(row >= Nn) return;
    const float* xr = x + (size_t)row*Ff;
    float a0=0,a1=0,a2=0,a3=0,a4=0,a5=0;
    for(int k = lane; k < Ff; k += 32){
        float xv = xr[k];
        const float* w = Ws + k*Hh;
        a0 += xv*w[0]; a1 += xv*w[1]; a2 += xv*w[2];
        a3 += xv*w[3]; a4 += xv*w[4]; a5 += xv*w[5];
    }
    #pragma unroll
    for(int off = 16; off; off >>= 1){
        a0 += __shfl_down_sync(0xffffffffu, a0, off);
        a1 += __shfl_down_sync(0xffffffffu, a1, off);
        a2 += __shfl_down_sync(0xffffffffu, a2, off);
        a3 += __shfl_down_sync(0xffffffffu, a3, off);
        a4 += __shfl_down_sync(0xffffffffu, a4, off);
        a5 += __shfl_down_sync(0xffffffffu, a5, off);
    }
    if(lane == 0){
        float* o = t1 + (size_t)row*Hh;
        o[0]=a0; o[1]=a1; o[2]=a2; o[3]=a3; o[4]=a4; o[5]=a5;
    }
}

// ---------------- layer-2 fused: dinv + t2 = x1 @ W2 ---------------------------
__global__ void zDinvGemm2(const unsigned char* __restrict__ nv,
                           const float* __restrict__ x1, const float* __restrict__ W2,
                           float* __restrict__ t2){
    int v = blockIdx.x*blockDim.x + threadIdx.x;
    if(v >= Nn) return;
    int add = (nv[v] && !g_hasloop[v]) ? 1 : 0;
    g_addloop[v] = (unsigned char)add;
    int dg = g_degI[v] + add;
    g_dinv[v] = (dg > 0) ? 1.0f/sqrtf((float)dg) : 0.0f;
    float xr[Hh];
    #pragma unroll
    for(int j = 0; j < Hh; j++) xr[j] = x1[v*Hh + j];
    #pragma unroll
    for(int c = 0; c < Cc; c++){
        float a = 0.f;
        #pragma unroll
        for(int j = 0; j < Hh; j++) a += xr[j]*W2[j*Cc + c];
        t2[v*Cc + c] = a;
    }
}

// ---------------- degree / dinv (stage 1: all nodes valid) ----------------
__global__ void zDeg(const int* __restrict__ sA, const int* __restrict__ dA){
    int e = blockIdx.x*blockDim.x + threadIdx.x;
    if(e >= Ee) return;
    int d = dA[e];
    atomicAdd(&g_degI[d], 1);
    if(sA[e] == d) g_hasloop[d] = 1;
}

__global__ void zDinv1(){
    int v = blockIdx.x*blockDim.x + threadIdx.x;
    if(v >= Nn) return;
    int add = g_hasloop[v] ? 0 : 1;
    g_addloop[v] = (unsigned char)add;
    int dg = g_degI[v] + add;
    g_dinv[v] = (dg > 0) ? 1.0f/sqrtf((float)dg) : 0.0f;
}

template<int FD>
__global__ void zAgg(const int* __restrict__ sA, const int* __restrict__ dA,
                     const unsigned char* __restrict__ ev,
                     const float* __restrict__ t, float* __restrict__ acc){
    int e = blockIdx.x*blockDim.x + threadIdx.x;
    if(e >= Ee) return;
    if(ev && !ev[e]) return;
    int s = sA[e], d = dA[e];
    float c = g_dinv[s]*g_dinv[d];
    #pragma unroll
    for(int j = 0; j < FD; j++)
        atomicAdd(&acc[(size_t)d*FD + j], t[(size_t)s*FD + j]*c);
}

template<int FD, bool RELU>
__global__ void zFinishGcn(const float* __restrict__ acc, const float* __restrict__ t,
                           const float* __restrict__ bias, float* __restrict__ out){
    int v = blockIdx.x*blockDim.x + threadIdx.x;
    if(v >= Nn) return;
    float di = g_dinv[v];
    float al = g_addloop[v] ? di*di : 0.0f;
    #pragma unroll
    for(int j = 0; j < FD; j++){
        float o = acc[(size_t)v*FD + j] + al*t[(size_t)v*FD + j] + bias[j];
        out[(size_t)v*FD + j] = RELU ? fmaxf(o, 0.0f) : o;
    }
}

// ---------------- edge pool pass 1: raw -> exp -> segment sum + adjacency counts
// (softmax max-shift eliminated: score invariant to it; raw is O(1))
template<int FD>
__global__ void zPass1(const float* __restrict__ xf, const int* __restrict__ sA,
                       const int* __restrict__ dA, const unsigned char* __restrict__ ev,
                       const float* __restrict__ Wp, const float* __restrict__ bp){
    int e = blockIdx.x*blockDim.x + threadIdx.x;
    if(e >= Ee) return;
    bool valid = ev ? (ev[e] != 0) : true;
    float exv = 0.0f;
    if(valid){
        int s = sA[e], d = dA[e];
        float r = bp[0];
        #pragma unroll
        for(int j = 0; j < FD; j++) r += xf[(size_t)s*FD + j]*Wp[j];
        #pragma unroll
        for(int j = 0; j < FD; j++) r += xf[(size_t)d*FD + j]*Wp[FD + j];
        exv = expf(r);
        atomicAdd(&g_s[d], exv);
        atomicAdd(&g_adjCnt[s], 1);
        if(d != s) atomicAdd(&g_adjCnt[d], 1);
    }
    g_ex[e] = exv;
}

// ---------------- 3-kernel exclusive scan of adjCnt -> off/cur ------------------
__global__ void zScanA(){
    __shared__ int sh[NT];
    int v = blockIdx.x*NT + threadIdx.x;
    int c = (v < Nn) ? g_adjCnt[v] : 0;
    sh[threadIdx.x] = c; __syncthreads();
    for(int o = NT/2; o; o >>= 1){
        if(threadIdx.x < o) sh[threadIdx.x] += sh[threadIdx.x + o];
        __syncthreads();
    }
    if(threadIdx.x == 0) g_bsum[blockIdx.x] = sh[0];
}
__global__ void zScanB(){
    __shared__ int sh[NT];
    int t = threadIdx.x;
    int val = (t < NB) ? g_bsum[t] : 0;
    sh[t] = val; __syncthreads();
    for(int o = 1; o < NT; o <<= 1){
        int x = (t >= o) ? sh[t - o] : 0;
        __syncthreads(); sh[t] += x; __syncthreads();
    }
    if(t < NB) g_bsum[t] = sh[t] - val;   // exclusive
}
__global__ void zScanC(){
    __shared__ int sh[NT];
    int v = blockIdx.x*NT + threadIdx.x;
    int c = (v < Nn) ? g_adjCnt[v] : 0;
    sh[threadIdx.x] = c; __syncthreads();
    for(int o = 1; o < NT; o <<= 1){
        int x = (threadIdx.x >= o) ? sh[threadIdx.x - o] : 0;
        __syncthreads(); sh[threadIdx.x] += x; __syncthreads();
    }
    int excl = sh[threadIdx.x] - c + g_bsum[blockIdx.x];
    if(v < Nn){ g_off[v] = excl; g_cur[v] = excl; }
    if(v == Nn - 1) g_off[Nn] = excl + c;
}

// ---------------- pass 2: score + prio + CSR adjacency fill --------------------
__global__ void zFill(const int* __restrict__ sA, const int* __restrict__ dA,
                      const unsigned char* __restrict__ ev){
    int e = blockIdx.x*blockDim.x + threadIdx.x;
    if(e >= Ee) return;
    bool valid = ev ? (ev[e] != 0) : true;
    if(!valid) return;
    int s = sA[e], d = dA[e];
    float sv = g_s[d];
    float sc = g_ex[e]/((sv > 0.f) ? sv : 1.f) + 0.5f;
    g_score[e] = sc;
    // total priority = (score desc, edge index asc) == stable argsort(-score)
    unsigned long long p = ((unsigned long long)fkey(sc) << 32)
                         | (unsigned long long)(0xFFFFFFFFu - (unsigned)e);
    int slot = atomicAdd(&g_cur[s], 1);
    g_adjP[slot] = p; g_adjO[slot] = d;
    if(d != s){
        slot = atomicAdd(&g_cur[d], 1);
        g_adjP[slot] = p; g_adjO[slot] = s;
    }
}

// ---------------- Suitor matching (== sequential greedy; no barriers) ----------
// Single-ownership: a node is re-processed only by the thread that displaced its
// accepted proposal; suitor values are monotonically increasing (atomicMax), so
// stale volatile reads are <= current and can never cause a false skip.
__global__ void zSuitor(const int* __restrict__ sA, const int* __restrict__ dA){
    int u = blockIdx.x*blockDim.x + threadIdx.x;
    if(u >= Nn) return;
    while(true){
        int lo = g_off[u], hi = g_off[u+1];
        unsigned long long best = 0ull; int bestv = -1;
        for(int i = lo; i < hi; i++){
            unsigned long long p = g_adjP[i];
            if(p <= best) continue;
            int w = g_adjO[i];
            if(p > *((volatile unsigned long long*)&g_suitor[w])){ best = p; bestv = w; }
        }
        if(bestv < 0) break;
        unsigned long long old = atomicMax(&g_suitor[bestv], best);
        if(old < best){
            if(old == 0ull) break;
            int e = (int)(0xFFFFFFFFu - (unsigned)(old & 0xFFFFFFFFull));
            int s = sA[e], d = dA[e];
            u = (s == bestv) ? d : s;   // take over displaced proposer
        }
        // else: lost the race — rescan the same u
    }
}

// ---------------- pool node + match extraction (+ next-stage resets) -----------
template<int FD, bool HAVENV, bool RESETNEXT>
__global__ void zPoolNode(const float* __restrict__ xin, float* __restrict__ xout,
                          const unsigned char* __restrict__ nvin, unsigned char* __restrict__ nvout,
                          const int* __restrict__ sA, const int* __restrict__ dA){
    int v = blockIdx.x*blockDim.x + threadIdx.x;
    if(v >= Nn) return;
    unsigned long long p = g_suitor[v];
    float scl = 1.0f; int prt = -1; bool deadv = false; int cm = v;
    if(p != 0ull){
        int e = (int)(0xFFFFFFFFu - (unsigned)(p & 0xFFFFFFFFull));
        int s = sA[e], d = dA[e];
        if(g_suitor[s] == p && g_suitor[d] == p){    // mutual => matched via e
            if(v == s){ scl = g_score[e]; if(d != s) prt = d; }
            else if(v == d && s != d){ deadv = true; cm = s; }
        }
    }
    bool nvbase = HAVENV ? (nvin[v] != 0) : true;
    unsigned char nv = (nvbase && !deadv) ? 1 : 0;
    nvout[v] = nv;
    g_cmap[v] = cm;
    #pragma unroll
    for(int j = 0; j < FD; j++){
        float val = xin[(size_t)v*FD + j] + ((prt >= 0) ? xin[(size_t)prt*FD + j] : 0.0f);
        xout[(size_t)v*FD + j] = nv ? val*scl : 0.0f;
    }
    if(RESETNEXT){
        g_suitor[v] = 0ull; g_s[v] = 0.f; g_adjCnt[v] = 0;
        g_degI[v] = 0; g_hasloop[v] = 0;
    }
}

// ---------------- remap + dedup (hash; representative = min original index) ------
__global__ void zRemapHash(const int* __restrict__ sA, const int* __restrict__ dA){
    int e = blockIdx.x*blockDim.x + threadIdx.x;
    if(e >= Ee) return;
    int ns = g_cmap[sA[e]];
    int nd = g_cmap[dA[e]];
    g_ns[e] = ns; g_nd[e] = nd;
    unsigned key = (unsigned)ns*60000u + (unsigned)nd;
    unsigned h = (key*2654435761u) & TABM;
    while(true){
        unsigned old = atomicCAS(&g_hkey[h], 0xFFFFFFFFu, key);
        if(old == 0xFFFFFFFFu || old == key){
            atomicMin(&g_hval[h], (unsigned)e);
            break;
        }
        h = (h + 1u) & TABM;
    }
}

// dedup + layer-2 degree counting fused
__global__ void zDedup(){
    int e = blockIdx.x*blockDim.x + threadIdx.x;
    if(e >= Ee) return;
    int ns = g_ns[e], nd = g_nd[e];
    unsigned key = (unsigned)ns*60000u + (unsigned)nd;
    unsigned h = (key*2654435761u) & TABM;
    while(g_hkey[h] != key) h = (h + 1u) & TABM;
    unsigned char ev = (g_hval[h] == (unsigned)e) ? 1 : 0;
    g_ev1[e] = ev;
    if(ev){
        atomicAdd(&g_degI[nd], 1);
        if(ns == nd) g_hasloop[nd] = 1;
    }
}

// ---------------- final pooling + log_softmax ----------------
__global__ void zPoolBatch(const int* __restrict__ batch, const float* __restrict__ x2){
    __shared__ float sc[Bb];
    __shared__ float ss[Bb*Cc];
    int t = threadIdx.x;
    if(t < Bb)    sc[t] = 0.f;
    if(t < Bb*Cc) ss[t] = 0.f;
    __syncthreads();
    for(int v = blockIdx.x*blockDim.x + t; v < Nn; v += gridDim.x*blockDim.x){
        if(g_nv2[v]){
            int b = batch[v];
            atomicAdd(&sc[b], 1.0f);
            #pragma unroll
            for(int c = 0; c < Cc; c++)
                atomicAdd(&ss[b*Cc + c], x2[(size_t)v*Cc + c]);
        }
    }
    __syncthreads();
    if(t < Bb)    atomicAdd(&g_cnt[t], sc[t]);
    if(t < Bb*Cc) atomicAdd(&g_sum[t], ss[t]);
}

__global__ void zFinal(float* __restrict__ out){
    __shared__ float gs[Bb*Cc];
    __shared__ float lse[Bb];
    int t = threadIdx.x;
    if(t < Bb*Cc) gs[t] = g_sum[t]/g_cnt[t/Cc];
    __syncthreads();
    if(t < Bb){
        float m = -1e30f;
        for(int c = 0; c < Cc; c++) m = fmaxf(m, gs[t*Cc + c]);
        float s = 0.f;
        for(int c = 0; c < Cc; c++) s += expf(gs[t*Cc + c] - m);
        lse[t] = m + logf(s);
    }
    __syncthreads();
    if(t < Bb*Cc) out[t] = gs[t] - lse[t/Cc];
}

// ---------------- launch ----------------
extern "C" void kernel_launch(void* const* d_in, const int* in_sizes, int n_in,
                              void* d_out, int out_size){
    (void)in_sizes; (void)n_in; (void)out_size;
    const float* x    = (const float*)d_in[0];
    const int*   src  = (const int*)  d_in[1];
    const int*   dst  = (const int*)  d_in[2];
    const int*   bat  = (const int*)  d_in[3];
    const float* W1   = (const float*)d_in[4];
    const float* b1   = (const float*)d_in[5];
    const float* W2   = (const float*)d_in[6];
    const float* b2   = (const float*)d_in[7];
    const float* Wp1  = (const float*)d_in[8];
    const float* bp1  = (const float*)d_in[9];
    const float* Wp2  = (const float*)d_in[10];
    const float* bp2  = (const float*)d_in[11];
    float* out = (float*)d_out;

    const int EB  = (Ee + NT - 1)/NT;
    const int IB  = (int)((TAB + NT - 1)/NT);

    // every device-global pointer passed as a kernel ARG must come from
    // cudaGetSymbolAddress (host symbol == host shadow under ATS!)
    float *pT1, *pAcc1, *pH1, *pX1, *pT2, *pAcc2, *pH2, *pX2;
    cudaGetSymbolAddress((void**)&pT1,   g_t1);
    cudaGetSymbolAddress((void**)&pAcc1, g_acc1);
    cudaGetSymbolAddress((void**)&pH1,   g_h1);
    cudaGetSymbolAddress((void**)&pX1,   g_x1);
    cudaGetSymbolAddress((void**)&pT2,   g_t2);
    cudaGetSymbolAddress((void**)&pAcc2, g_acc2);
    cudaGetSymbolAddress((void**)&pH2,   g_h2);
    cudaGetSymbolAddress((void**)&pX2,   g_x2);
    int *pNs, *pNd;
    cudaGetSymbolAddress((void**)&pNs, g_ns);
    cudaGetSymbolAddress((void**)&pNd, g_nd);
    unsigned char *pEv1, *pNv1, *pNv2;
    cudaGetSymbolAddress((void**)&pEv1, g_ev1);
    cudaGetSymbolAddress((void**)&pNv1, g_nv1);
    cudaGetSymbolAddress((void**)&pNv2, g_nv2);

    zInitMain<<<IB, NT>>>();

    // ---- GCN layer 1 + relu ----
    zGemm1<<<Nn/8, NT>>>(x, W1, pT1);
    zDeg<<<EB, NT>>>(src, dst);
    zDinv1<<<NB, NT>>>();
    zAgg<Hh><<<EB, NT>>>(src, dst, nullptr, pT1, pAcc1);
    zFinishGcn<Hh, true><<<NB, NT>>>(pAcc1, pT1, b1, pH1);

    // ---- EdgePool 1 (suitor) ----
    zPass1<Hh><<<EB, NT>>>(pH1, src, dst, nullptr, Wp1, bp1);
    zScanA<<<NB, NT>>>();
    zScanB<<<1, NT>>>();
    zScanC<<<NB, NT>>>();
    zFill<<<EB, NT>>>(src, dst, nullptr);
    zSuitor<<<NB, NT>>>(src, dst);
    zPoolNode<Hh, false, true><<<NB, NT>>>(pH1, pX1, nullptr, pNv1, src, dst);

    // ---- remap + dedup (+ layer-2 degrees) ----
    zRemapHash<<<EB, NT>>>(src, dst);
    zDedup<<<EB, NT>>>();

    // ---- GCN layer 2 (dinv fused with gemm2) ----
    zDinvGemm2<<<NB, NT>>>(pNv1, pX1, W2, pT2);
    zAgg<Cc><<<EB, NT>>>(pNs, pNd, pEv1, pT2, pAcc2);
    zFinishGcn<Cc, false><<<NB, NT>>>(pAcc2, pT2, b2, pH2);

    // ---- EdgePool 2 (suitor) ----
    zPass1<Cc><<<EB, NT>>>(pH2, pNs, pNd, pEv1, Wp2, bp2);
    zScanA<<<NB, NT>>>();
    zScanB<<<1, NT>>>();
    zScanC<<<NB, NT>>>();
    zFill<<<EB, NT>>>(pNs, pNd, pEv1);
    zSuitor<<<NB, NT>>>(pNs, pNd);
    zPoolNode<Cc, true, false><<<NB, NT>>>(pH2, pX2, pNv1, pNv2, pNs, pNd);

    // ---- mean pool + log_softmax ----
    zPoolBatch<<<NB, NT>>>(bat, pX2);
    zFinal<<<1, 128>>>(out);
}

// round 16
// speedup vs baseline: 1.6925x; 1.4707x over previous
// GCN + EdgePool forward — R16: scan-free CSR (atomic cursor), counting fused
// into zDeg/zDedup, packed 16B adjacency entries for suitor. 21 launches.
#include <cuda_runtime.h>
#include <math.h>

#define Nn 60000
#define Ee 600000
#define AE (2*Ee)
#define Ff 384
#define Hh 6
#define Cc 10
#define Bb 8
#define TAB (1u<<21)
#define TABM (TAB-1u)
#define NT 256
#define NB ((Nn + NT - 1)/NT)

// ---------------- scratch (static device globals; no allocation) ----------------
__device__ float g_t1[Nn*Hh];
__device__ float g_acc1[Nn*Hh];
__device__ float g_h1[Nn*Hh];
__device__ float g_x1[Nn*Hh];
__device__ float g_t2[Nn*Cc];
__device__ float g_acc2[Nn*Cc];
__device__ float g_h2[Nn*Cc];
__device__ float g_x2[Nn*Cc];

__device__ int   g_degI[Nn];
__device__ int   g_hasloop[Nn];
__device__ unsigned char g_addloop[Nn];
__device__ float g_dinv[Nn];

__device__ float g_s[Nn];
__device__ float g_ex[Ee];
__device__ float g_score[Ee];

__device__ unsigned long long g_suitor[Nn];
__device__ int g_adjCnt[Nn];
__device__ int g_off[Nn];
__device__ int g_cur[Nn];
__device__ int g_cursor;
__device__ ulonglong2 g_adj[AE];      // {prio, other}

__device__ int   g_cmap[Nn];
__device__ int   g_ns[Ee];
__device__ int   g_nd[Ee];
__device__ unsigned char g_ev1[Ee];
__device__ unsigned char g_nv1[Nn];
__device__ unsigned char g_nv2[Nn];

__device__ unsigned g_hkey[TAB];
__device__ unsigned g_hval[TAB];

__device__ float g_cnt[Bb];
__device__ float g_sum[Bb*Cc];

// ---------------- helpers ----------------
__device__ __forceinline__ unsigned fkey(float f){
    unsigned b = __float_as_uint(f);
    return b ^ (((int)b >> 31) ? 0xFFFFFFFFu : 0x80000000u);
}

// ---------------- init ----------------
__global__ void zInitMain(){
    int stride = gridDim.x*blockDim.x;
    for(unsigned i = blockIdx.x*blockDim.x + threadIdx.x; i < TAB; i += stride){
        g_hkey[i] = 0xFFFFFFFFu; g_hval[i] = 0xFFFFFFFFu;
        if(i < Nn*Cc) g_acc2[i] = 0.f;
        if(i < Nn*Hh) g_acc1[i] = 0.f;
        if(i < Nn){
            g_degI[i]=0; g_hasloop[i]=0; g_s[i]=0.f;
            g_suitor[i]=0ull; g_adjCnt[i]=0;
        }
        if(i < Bb)    g_cnt[i]=0.f;
        if(i < Bb*Cc) g_sum[i]=0.f;
        if(i == 0)    g_cursor = 0;
    }
}

// ---------------- GEMM1: t1 = x @ W1  (60000x384 @ 384x6, exact fp32) ----------
__global__ void zGemm1(const float* __restrict__ x, const float* __restrict__ W1,
                       float* __restrict__ t1){
    __shared__ float Ws[Ff*Hh];
    for(int i = threadIdx.x; i < Ff*Hh; i += blockDim.x) Ws[i] = W1[i];
    __syncthreads();
    int warp = threadIdx.x >> 5, lane = threadIdx.x & 31;
    int row = blockIdx.x*8 + warp;
    if(row >= Nn) return;
    const float* xr = x + (size_t)row*Ff;
    float a0=0,a1=0,a2=0,a3=0,a4=0,a5=0;
    for(int k = lane; k < Ff; k += 32){
        float xv = xr[k];
        const float* w = Ws + k*Hh;
        a0 += xv*w[0]; a1 += xv*w[1]; a2 += xv*w[2];
        a3 += xv*w[3]; a4 += xv*w[4]; a5 += xv*w[5];
    }
    #pragma unroll
    for(int off = 16; off; off >>= 1){
        a0 += __shfl_down_sync(0xffffffffu, a0, off);
        a1 += __shfl_down_sync(0xffffffffu, a1, off);
        a2 += __shfl_down_sync(0xffffffffu, a2, off);
        a3 += __shfl_down_sync(0xffffffffu, a3, off);
        a4 += __shfl_down_sync(0xffffffffu, a4, off);
        a5 += __shfl_down_sync(0xffffffffu, a5, off);
    }
    if(lane == 0){
        float* o = t1 + (size_t)row*Hh;
        o[0]=a0; o[1]=a1; o[2]=a2; o[3]=a3; o[4]=a4; o[5]=a5;
    }
}

// ---------------- stage-1 degree + adjacency counts ----------------
__global__ void zDeg(const int* __restrict__ sA, const int* __restrict__ dA){
    int e = blockIdx.x*blockDim.x + threadIdx.x;
    if(e >= Ee) return;
    int s = sA[e], d = dA[e];
    atomicAdd(&g_degI[d], 1);
    if(s == d) g_hasloop[d] = 1;
    atomicAdd(&g_adjCnt[s], 1);
    if(d != s) atomicAdd(&g_adjCnt[d], 1);
}

// stage-1: dinv + CSR offset assignment (unordered cursor)
__global__ void zDinv1(){
    int v = blockIdx.x*blockDim.x + threadIdx.x;
    if(v >= Nn) return;
    int add = g_hasloop[v] ? 0 : 1;
    g_addloop[v] = (unsigned char)add;
    int dg = g_degI[v] + add;
    g_dinv[v] = (dg > 0) ? 1.0f/sqrtf((float)dg) : 0.0f;
    int c = g_adjCnt[v];
    int off = c ? atomicAdd(&g_cursor, c) : 0;
    g_off[v] = off; g_cur[v] = off;
}

// ---------------- layer-2 fused: dinv + offsets + t2 = x1 @ W2 ------------------
__global__ void zDinvGemm2(const unsigned char* __restrict__ nv,
                           const float* __restrict__ x1, const float* __restrict__ W2,
                           float* __restrict__ t2){
    int v = blockIdx.x*blockDim.x + threadIdx.x;
    if(v >= Nn) return;
    int add = (nv[v] && !g_hasloop[v]) ? 1 : 0;
    g_addloop[v] = (unsigned char)add;
    int dg = g_degI[v] + add;
    g_dinv[v] = (dg > 0) ? 1.0f/sqrtf((float)dg) : 0.0f;
    int c = g_adjCnt[v];
    int off = c ? atomicAdd(&g_cursor, c) : 0;
    g_off[v] = off; g_cur[v] = off;
    float xr[Hh];
    #pragma unroll
    for(int j = 0; j < Hh; j++) xr[j] = x1[v*Hh + j];
    #pragma unroll
    for(int c2 = 0; c2 < Cc; c2++){
        float a = 0.f;
        #pragma unroll
        for(int j = 0; j < Hh; j++) a += xr[j]*W2[j*Cc + c2];
        t2[v*Cc + c2] = a;
    }
}

template<int FD>
__global__ void zAgg(const int* __restrict__ sA, const int* __restrict__ dA,
                     const unsigned char* __restrict__ ev,
                     const float* __restrict__ t, float* __restrict__ acc){
    int e = blockIdx.x*blockDim.x + threadIdx.x;
    if(e >= Ee) return;
    if(ev && !ev[e]) return;
    int s = sA[e], d = dA[e];
    float c = g_dinv[s]*g_dinv[d];
    #pragma unroll
    for(int j = 0; j < FD; j++)
        atomicAdd(&acc[(size_t)d*FD + j], t[(size_t)s*FD + j]*c);
}

template<int FD, bool RELU>
__global__ void zFinishGcn(const float* __restrict__ acc, const float* __restrict__ t,
                           const float* __restrict__ bias, float* __restrict__ out){
    int v = blockIdx.x*blockDim.x + threadIdx.x;
    if(v >= Nn) return;
    float di = g_dinv[v];
    float al = g_addloop[v] ? di*di : 0.0f;
    #pragma unroll
    for(int j = 0; j < FD; j++){
        float o = acc[(size_t)v*FD + j] + al*t[(size_t)v*FD + j] + bias[j];
        out[(size_t)v*FD + j] = RELU ? fmaxf(o, 0.0f) : o;
    }
}

// ---------------- edge pool pass 1: raw -> exp -> segment sum -------------------
// (softmax max-shift eliminated: score invariant to it; raw is O(1))
template<int FD>
__global__ void zPass1(const float* __restrict__ xf, const int* __restrict__ sA,
                       const int* __restrict__ dA, const unsigned char* __restrict__ ev,
                       const float* __restrict__ Wp, const float* __restrict__ bp){
    int e = blockIdx.x*blockDim.x + threadIdx.x;
    if(e >= Ee) return;
    bool valid = ev ? (ev[e] != 0) : true;
    float exv = 0.0f;
    if(valid){
        int s = sA[e], d = dA[e];
        float r = bp[0];
        #pragma unroll
        for(int j = 0; j < FD; j++) r += xf[(size_t)s*FD + j]*Wp[j];
        #pragma unroll
        for(int j = 0; j < FD; j++) r += xf[(size_t)d*FD + j]*Wp[FD + j];
        exv = expf(r);
        atomicAdd(&g_s[d], exv);
    }
    g_ex[e] = exv;
}

// ---------------- pass 2: score + prio + CSR adjacency fill (packed 16B) --------
__global__ void zFill(const int* __restrict__ sA, const int* __restrict__ dA,
                      const unsigned char* __restrict__ ev){
    int e = blockIdx.x*blockDim.x + threadIdx.x;
    if(e >= Ee) return;
    bool valid = ev ? (ev[e] != 0) : true;
    if(!valid) return;
    int s = sA[e], d = dA[e];
    float sv = g_s[d];
    float sc = g_ex[e]/((sv > 0.f) ? sv : 1.f) + 0.5f;
    g_score[e] = sc;
    // total priority = (score desc, edge index asc) == stable argsort(-score)
    unsigned long long p = ((unsigned long long)fkey(sc) << 32)
                         | (unsigned long long)(0xFFFFFFFFu - (unsigned)e);
    int slot = atomicAdd(&g_cur[s], 1);
    g_adj[slot] = make_ulonglong2(p, (unsigned long long)(unsigned)d);
    if(d != s){
        slot = atomicAdd(&g_cur[d], 1);
        g_adj[slot] = make_ulonglong2(p, (unsigned long long)(unsigned)s);
    }
}

// ---------------- Suitor matching (== sequential greedy; no barriers) ----------
// Single-ownership: a node is re-processed only by the thread that displaced its
// accepted proposal; suitor values are monotonically increasing (atomicMax), so
// stale volatile reads are <= current and can never cause a false skip.
__global__ void zSuitor(const int* __restrict__ sA, const int* __restrict__ dA){
    int u = blockIdx.x*blockDim.x + threadIdx.x;
    if(u >= Nn) return;
    while(true){
        int lo = g_off[u], hi = lo + g_adjCnt[u];
        unsigned long long best = 0ull; int bestv = -1;
        for(int i = lo; i < hi; i++){
            ulonglong2 a = g_adj[i];
            if(a.x <= best) continue;
            int w = (int)a.y;
            if(a.x > *((volatile unsigned long long*)&g_suitor[w])){ best = a.x; bestv = w; }
        }
        if(bestv < 0) break;
        unsigned long long old = atomicMax(&g_suitor[bestv], best);
        if(old < best){
            if(old == 0ull) break;
            int e = (int)(0xFFFFFFFFu - (unsigned)(old & 0xFFFFFFFFull));
            int s = sA[e], d = dA[e];
            u = (s == bestv) ? d : s;   // take over displaced proposer
        }
        // else: lost the race — rescan the same u
    }
}

// ---------------- pool node + match extraction (+ next-stage resets) -----------
template<int FD, bool HAVENV, bool RESETNEXT>
__global__ void zPoolNode(const float* __restrict__ xin, float* __restrict__ xout,
                          const unsigned char* __restrict__ nvin, unsigned char* __restrict__ nvout,
                          const int* __restrict__ sA, const int* __restrict__ dA){
    int v = blockIdx.x*blockDim.x + threadIdx.x;
    if(v >= Nn) return;
    unsigned long long p = g_suitor[v];
    float scl = 1.0f; int prt = -1; bool deadv = false; int cm = v;
    if(p != 0ull){
        int e = (int)(0xFFFFFFFFu - (unsigned)(p & 0xFFFFFFFFull));
        int s = sA[e], d = dA[e];
        if(g_suitor[s] == p && g_suitor[d] == p){    // mutual => matched via e
            if(v == s){ scl = g_score[e]; if(d != s) prt = d; }
            else if(v == d && s != d){ deadv = true; cm = s; }
        }
    }
    bool nvbase = HAVENV ? (nvin[v] != 0) : true;
    unsigned char nv = (nvbase && !deadv) ? 1 : 0;
    nvout[v] = nv;
    g_cmap[v] = cm;
    #pragma unroll
    for(int j = 0; j < FD; j++){
        float val = xin[(size_t)v*FD + j] + ((prt >= 0) ? xin[(size_t)prt*FD + j] : 0.0f);
        xout[(size_t)v*FD + j] = nv ? val*scl : 0.0f;
    }
    if(RESETNEXT){
        g_suitor[v] = 0ull; g_s[v] = 0.f; g_adjCnt[v] = 0;
        g_degI[v] = 0; g_hasloop[v] = 0;
        if(v == 0) g_cursor = 0;
    }
}

// ---------------- remap + dedup (hash; representative = min original index) ------
__global__ void zRemapHash(const int* __restrict__ sA, const int* __restrict__ dA){
    int e = blockIdx.x*blockDim.x + threadIdx.x;
    if(e >= Ee) return;
    int ns = g_cmap[sA[e]];
    int nd = g_cmap[dA[e]];
    g_ns[e] = ns; g_nd[e] = nd;
    unsigned key = (unsigned)ns*60000u + (unsigned)nd;
    unsigned h = (key*2654435761u) & TABM;
    while(true){
        unsigned old = atomicCAS(&g_hkey[h], 0xFFFFFFFFu, key);
        if(old == 0xFFFFFFFFu || old == key){
            atomicMin(&g_hval[h], (unsigned)e);
            break;
        }
        h = (h + 1u) & TABM;
    }
}

// dedup + layer-2 degree AND adjacency counting fused
__global__ void zDedup(){
    int e = blockIdx.x*blockDim.x + threadIdx.x;
    if(e >= Ee) return;
    int ns = g_ns[e], nd = g_nd[e];
    unsigned key = (unsigned)ns*60000u + (unsigned)nd;
    unsigned h = (key*2654435761u) & TABM;
    while(g_hkey[h] != key) h = (h + 1u) & TABM;
    unsigned char ev = (g_hval[h] == (unsigned)e) ? 1 : 0;
    g_ev1[e] = ev;
    if(ev){
        atomicAdd(&g_degI[nd], 1);
        if(ns == nd) g_hasloop[nd] = 1;
        atomicAdd(&g_adjCnt[ns], 1);
        if(nd != ns) atomicAdd(&g_adjCnt[nd], 1);
    }
}

// ---------------- final pooling + log_softmax ----------------
__global__ void zPoolBatch(const int* __restrict__ batch, const float* __restrict__ x2){
    __shared__ float sc[Bb];
    __shared__ float ss[Bb*Cc];
    int t = threadIdx.x;
    if(t < Bb)    sc[t] = 0.f;
    if(t < Bb*Cc) ss[t] = 0.f;
    __syncthreads();
    for(int v = blockIdx.x*blockDim.x + t; v < Nn; v += gridDim.x*blockDim.x){
        if(g_nv2[v]){
            int b = batch[v];
            atomicAdd(&sc[b], 1.0f);
            #pragma unroll
            for(int c = 0; c < Cc; c++)
                atomicAdd(&ss[b*Cc + c], x2[(size_t)v*Cc + c]);
        }
    }
    __syncthreads();
    if(t < Bb)    atomicAdd(&g_cnt[t], sc[t]);
    if(t < Bb*Cc) atomicAdd(&g_sum[t], ss[t]);
}

__global__ void zFinal(float* __restrict__ out){
    __shared__ float gs[Bb*Cc];
    __shared__ float lse[Bb];
    int t = threadIdx.x;
    if(t < Bb*Cc) gs[t] = g_sum[t]/g_cnt[t/Cc];
    __syncthreads();
    if(t < Bb){
        float m = -1e30f;
        for(int c = 0; c < Cc; c++) m = fmaxf(m, gs[t*Cc + c]);
        float s = 0.f;
        for(int c = 0; c < Cc; c++) s += expf(gs[t*Cc + c] - m);
        lse[t] = m + logf(s);
    }
    __syncthreads();
    if(t < Bb*Cc) out[t] = gs[t] - lse[t/Cc];
}

// ---------------- launch ----------------
extern "C" void kernel_launch(void* const* d_in, const int* in_sizes, int n_in,
                              void* d_out, int out_size){
    (void)in_sizes; (void)n_in; (void)out_size;
    const float* x    = (const float*)d_in[0];
    const int*   src  = (const int*)  d_in[1];
    const int*   dst  = (const int*)  d_in[2];
    const int*   bat  = (const int*)  d_in[3];
    const float* W1   = (const float*)d_in[4];
    const float* b1   = (const float*)d_in[5];
    const float* W2   = (const float*)d_in[6];
    const float* b2   = (const float*)d_in[7];
    const float* Wp1  = (const float*)d_in[8];
    const float* bp1  = (const float*)d_in[9];
    const float* Wp2  = (const float*)d_in[10];
    const float* bp2  = (const float*)d_in[11];
    float* out = (float*)d_out;

    const int EB  = (Ee + NT - 1)/NT;
    const int IB  = (int)((TAB + NT - 1)/NT);

    // every device-global pointer passed as a kernel ARG must come from
    // cudaGetSymbolAddress (host symbol == host shadow under ATS!)
    float *pT1, *pAcc1, *pH1, *pX1, *pT2, *pAcc2, *pH2, *pX2;
    cudaGetSymbolAddress((void**)&pT1,   g_t1);
    cudaGetSymbolAddress((void**)&pAcc1, g_acc1);
    cudaGetSymbolAddress((void**)&pH1,   g_h1);
    cudaGetSymbolAddress((void**)&pX1,   g_x1);
    cudaGetSymbolAddress((void**)&pT2,   g_t2);
    cudaGetSymbolAddress((void**)&pAcc2, g_acc2);
    cudaGetSymbolAddress((void**)&pH2,   g_h2);
    cudaGetSymbolAddress((void**)&pX2,   g_x2);
    int *pNs, *pNd;
    cudaGetSymbolAddress((void**)&pNs, g_ns);
    cudaGetSymbolAddress((void**)&pNd, g_nd);
    unsigned char *pEv1, *pNv1, *pNv2;
    cudaGetSymbolAddress((void**)&pEv1, g_ev1);
    cudaGetSymbolAddress((void**)&pNv1, g_nv1);
    cudaGetSymbolAddress((void**)&pNv2, g_nv2);

    zInitMain<<<IB, NT>>>();

    // ---- GCN layer 1 + relu ----
    zGemm1<<<Nn/8, NT>>>(x, W1, pT1);
    zDeg<<<EB, NT>>>(src, dst);
    zDinv1<<<NB, NT>>>();
    zAgg<Hh><<<EB, NT>>>(src, dst, nullptr, pT1, pAcc1);
    zFinishGcn<Hh, true><<<NB, NT>>>(pAcc1, pT1, b1, pH1);

    // ---- EdgePool 1 (suitor) ----
    zPass1<Hh><<<EB, NT>>>(pH1, src, dst, nullptr, Wp1, bp1);
    zFill<<<EB, NT>>>(src, dst, nullptr);
    zSuitor<<<NB, NT>>>(src, dst);
    zPoolNode<Hh, false, true><<<NB, NT>>>(pH1, pX1, nullptr, pNv1, src, dst);

    // ---- remap + dedup (+ layer-2 degrees/adjacency) ----
    zRemapHash<<<EB, NT>>>(src, dst);
    zDedup<<<EB, NT>>>();

    // ---- GCN layer 2 (dinv + offsets fused with gemm2) ----
    zDinvGemm2<<<NB, NT>>>(pNv1, pX1, W2, pT2);
    zAgg<Cc><<<EB, NT>>>(pNs, pNd, pEv1, pT2, pAcc2);
    zFinishGcn<Cc, false><<<NB, NT>>>(pAcc2, pT2, b2, pH2);

    // ---- EdgePool 2 (suitor) ----
    zPass1<Cc><<<EB, NT>>>(pH2, pNs, pNd, pEv1, Wp2, bp2);
    zFill<<<EB, NT>>>(pNs, pNd, pEv1);
    zSuitor<<<NB, NT>>>(pNs, pNd);
    zPoolNode<Cc, true, false><<<NB, NT>>>(pH2, pX2, pNv1, pNv2, pNs, pNd);

    // ---- mean pool + log_softmax ----
    zPoolBatch<<<NB, NT>>>(bat, pX2);
    zFinal<<<1, 128>>>(out);
}